// round 12
// baseline (speedup 1.0000x reference)
#include <cuda_runtime.h>
#include <cuda_bf16.h>
#include <math.h>
#include <stdint.h>

// ---------------------------------------------------------------------------
// Problem constants (fixed shapes)
// ---------------------------------------------------------------------------
#define B_    128
#define N_    1022
#define NTIPS 512
#define H_    256
#define NH    8
#define HD    32
#define M1    (B_ * N_)        // 130816
#define M2    (B_ * (N_ - 1)) // 130688
#define LN_EPS 1e-5f

typedef __nv_bfloat16  bf16;
typedef __nv_bfloat162 bf162;

// ---------------------------------------------------------------------------
// Scratch (static device globals)
// ---------------------------------------------------------------------------
__device__ bf16  d_nfb[(size_t)M1 * NTIPS];     // node_features in bf16
__device__ bf16  d_t1b[(size_t)M1 * H_];        // elu(nf@w1+b1) bf16
__device__ float d_x  [(size_t)M1 * H_];        // ln(..) fp32 (edge reads)
__device__ bf16  d_xb [(size_t)M1 * H_];        // ln(..) bf16 (kv gemm A)
__device__ bf16  d_kvb[(size_t)M1 * 2 * H_];    // kv bf16 (attn reads)
__device__ bf16  d_eb [(size_t)M2 * 2 * H_];    // edge feats bf16 (r1 A); reused for e2b
__device__ float d_h  [(size_t)M2 * 2 * H_];    // r1 out fp32; reused for r2 out
__device__ bf16  d_hb [(size_t)M2 * 2 * H_];    // ln(elu(r1)) bf16 (r2 A)
__device__ float d_qv [H_];
__device__ float d_te [2 * H_];
__device__ float d_ctx[B_ * H_];
__device__ float d_nf [B_ * H_];
__device__ float d_lg [M2];
// transposed bf16 weights ([N][K], K contiguous)
__device__ bf16 d_w1t [H_ * NTIPS];
__device__ bf16 d_w2t [H_ * H_];
__device__ bf16 d_kvwt[2 * H_ * H_];
__device__ bf16 d_r1wt[2 * H_ * 2 * H_];
__device__ bf16 d_r2wt[2 * H_ * 2 * H_];

// ---------------------------------------------------------------------------
// helpers
// ---------------------------------------------------------------------------
__device__ __forceinline__ uint32_t smem_u32(const void* p) {
    uint32_t a;
    asm("{ .reg .u64 t; cvta.to.shared.u64 t, %1; cvt.u32.u64 %0, t; }"
        : "=r"(a) : "l"(p));
    return a;
}

__device__ __forceinline__ void mma_bf16(float* c, const uint32_t* a,
                                         const uint32_t* b) {
    asm volatile(
        "mma.sync.aligned.m16n8k16.row.col.f32.bf16.bf16.f32 "
        "{%0,%1,%2,%3}, {%4,%5,%6,%7}, {%8,%9}, {%0,%1,%2,%3};"
        : "+f"(c[0]), "+f"(c[1]), "+f"(c[2]), "+f"(c[3])
        : "r"(a[0]), "r"(a[1]), "r"(a[2]), "r"(a[3]), "r"(b[0]), "r"(b[1]));
}

#define CP_ASYNC16(dst, src) \
    asm volatile("cp.async.cg.shared.global [%0], [%1], 16;" \
        :: "r"(dst), "l"(src) : "memory")
#define CP_COMMIT() asm volatile("cp.async.commit_group;" ::: "memory")
#define CP_WAIT3()  asm volatile("cp.async.wait_group 3;" ::: "memory")

// ---------------------------------------------------------------------------
// bf16 tensor-core GEMM: C[M,Nn] = act(A[M,K] @ Bt[Nn,K]^T + bias)
// Block tile 128x128, BK=32, 256 threads (8 warps, 2m x 4n), warp 64x32,
// mma.m16n8k16.bf16. 4-stage cp.async ring, 2 CTAs/SM.
// SMEM per stage: A,B each [128][20] u32 (16 bf16-pairs + 4 pad).
// ---------------------------------------------------------------------------
#define BKC 32
#define LDS_STR 20
#define TILE_U32 (128 * LDS_STR)                 // 2560
#define STAGES 4
#define GEMM_SMEM (STAGES * 2 * TILE_U32 * 4)    // 81920 bytes

template <int ACT, bool WF32, bool WB16>  // ACT: 0 none, 1 elu
__global__ __launch_bounds__(256, 2)
void tc_gemm_kernel(const bf16* __restrict__ A, const bf16* __restrict__ Bt,
                    const float* __restrict__ bias,
                    float* __restrict__ Cf, bf16* __restrict__ Cb,
                    int M, int Nn, int K) {
    extern __shared__ uint32_t smem[];

    const int tid = threadIdx.x;
    const int bn = blockIdx.x, bm = blockIdx.y;

    // copy mapping: row = tid>>1 (0..127), 2x16B segs at (tid&1)*32 bytes
    const int crow = tid >> 1;
    const int chalf = tid & 1;
    const bf16* Ag = A + (size_t)(bm * 128 + crow) * K + chalf * 16;
    const bf16* Bg = Bt + (size_t)(bn * 128 + crow) * K + chalf * 16;

    const uint32_t sbase = smem_u32(smem);
    const uint32_t cbyte = (uint32_t)(crow * LDS_STR) * 4 + chalf * 32;

    // warp mapping
    const int wid = tid >> 5, lane = tid & 31;
    const int wm = (wid & 1) * 64;
    const int wn = (wid >> 1) * 32;
    const int g = lane >> 2, tig = lane & 3;

    float c[4][4][4];
    #pragma unroll
    for (int mt = 0; mt < 4; mt++)
        #pragma unroll
        for (int nt = 0; nt < 4; nt++)
            #pragma unroll
            for (int i = 0; i < 4; i++) c[mt][nt][i] = 0.f;

    const int NC = K >> 5;   // >= 8 for all calls

    // prologue: copy chunks 0..2 into stages 0..2
    #pragma unroll
    for (int p = 0; p < 3; p++) {
        const uint32_t ad = sbase + (uint32_t)p * 2 * TILE_U32 * 4 + cbyte;
        const uint32_t bd = ad + TILE_U32 * 4;
        const bf16* as = Ag + p * BKC;
        const bf16* bs = Bg + p * BKC;
        CP_ASYNC16(ad,      as);
        CP_ASYNC16(ad + 16, as + 8);
        CP_ASYNC16(bd,      bs);
        CP_ASYNC16(bd + 16, bs + 8);
        CP_COMMIT();
    }

    for (int kc = 0; kc < NC; kc++) {
        const int cur = kc & 3;

        // all warps done reading stage (kc+3)&3 (== chunk kc-1) before overwrite
        __syncthreads();
        if (kc + 3 < NC) {
            const int nst = (kc + 3) & 3;
            const uint32_t ad = sbase + (uint32_t)nst * 2 * TILE_U32 * 4 + cbyte;
            const uint32_t bd = ad + TILE_U32 * 4;
            const bf16* as = Ag + (kc + 3) * BKC;
            const bf16* bs = Bg + (kc + 3) * BKC;
            CP_ASYNC16(ad,      as);
            CP_ASYNC16(ad + 16, as + 8);
            CP_ASYNC16(bd,      bs);
            CP_ASYNC16(bd + 16, bs + 8);
        }
        CP_COMMIT();           // uniform group accounting (possibly empty)
        CP_WAIT3();            // chunk kc's group (4th most recent) complete
        __syncthreads();       // visibility of stage cur to all warps

        const uint32_t* Ab = smem + cur * 2 * TILE_U32;
        const uint32_t* Bb = Ab + TILE_U32;
        #pragma unroll
        for (int ks = 0; ks < 2; ks++) {      // two k16 steps per BK=32
            const int p0 = ks * 8;
            uint32_t a[4][4], b[4][2];
            #pragma unroll
            for (int mt = 0; mt < 4; mt++) {
                int r0 = wm + mt * 16 + g;
                a[mt][0] = Ab[(r0    ) * LDS_STR + p0 + tig];
                a[mt][1] = Ab[(r0 + 8) * LDS_STR + p0 + tig];
                a[mt][2] = Ab[(r0    ) * LDS_STR + p0 + tig + 4];
                a[mt][3] = Ab[(r0 + 8) * LDS_STR + p0 + tig + 4];
            }
            #pragma unroll
            for (int nt = 0; nt < 4; nt++) {
                int n0 = wn + nt * 8 + g;
                b[nt][0] = Bb[n0 * LDS_STR + p0 + tig];
                b[nt][1] = Bb[n0 * LDS_STR + p0 + tig + 4];
            }
            #pragma unroll
            for (int mt = 0; mt < 4; mt++)
                #pragma unroll
                for (int nt = 0; nt < 4; nt++)
                    mma_bf16(c[mt][nt], a[mt], b[nt]);
        }
    }

    // Epilogue: bias + optional ELU; fp32 and/or bf16 stores
    #pragma unroll
    for (int mt = 0; mt < 4; mt++) {
        #pragma unroll
        for (int nt = 0; nt < 4; nt++) {
            int col = bn * 128 + wn + nt * 8 + 2 * tig;
            float b0 = __ldg(bias + col), b1 = __ldg(bias + col + 1);
            #pragma unroll
            for (int half = 0; half < 2; half++) {
                int row = bm * 128 + wm + mt * 16 + g + half * 8;
                float v0 = c[mt][nt][half * 2 + 0] + b0;
                float v1 = c[mt][nt][half * 2 + 1] + b1;
                if (ACT == 1) {
                    v0 = v0 > 0.f ? v0 : expm1f(v0);
                    v1 = v1 > 0.f ? v1 : expm1f(v1);
                }
                if (WF32)
                    *(float2*)(Cf + (size_t)row * Nn + col) = make_float2(v0, v1);
                if (WB16)
                    *(bf162*)(Cb + (size_t)row * Nn + col) =
                        __floats2bfloat162_rn(v0, v1);
            }
        }
    }
}

// ---------------------------------------------------------------------------
// Weight transpose to bf16: out[n*K+k] = bf16(in[k*ldin + n])
// ---------------------------------------------------------------------------
__global__ __launch_bounds__(256)
void transpose_kernel(const float* __restrict__ in, bf16* __restrict__ out,
                      int K, int N, int ldin) {
    __shared__ float tile[32][33];
    int k0 = blockIdx.x * 32, n0 = blockIdx.y * 32;
    int x = threadIdx.x & 31, y = (threadIdx.x >> 5) * 4;
    #pragma unroll
    for (int i = 0; i < 4; i++)
        tile[y + i][x] = in[(size_t)(k0 + y + i) * ldin + n0 + x];
    __syncthreads();
    #pragma unroll
    for (int i = 0; i < 4; i++)
        out[(size_t)(n0 + y + i) * K + k0 + x] =
            __float2bfloat16_rn(tile[x][y + i]);
}

// ---------------------------------------------------------------------------
// fp32 -> bf16 elementwise convert (for node_features)
// ---------------------------------------------------------------------------
__global__ __launch_bounds__(256)
void cvt_kernel(const float* __restrict__ in, bf16* __restrict__ out) {
    size_t i = ((size_t)blockIdx.x * 256 + threadIdx.x) * 4;
    float4 v = *(const float4*)(in + i);
    *(bf162*)(out + i)     = __floats2bfloat162_rn(v.x, v.y);
    *(bf162*)(out + i + 2) = __floats2bfloat162_rn(v.z, v.w);
}

// ---------------------------------------------------------------------------
// Warp-per-row LayerNorm, optional ELU; fp32 in-place and/or bf16 copy out.
// 8 rows / block.
// ---------------------------------------------------------------------------
template <int W, bool DOELU, bool WF32, bool WB16>
__global__ __launch_bounds__(256)
void ln_warp_kernel(float* __restrict__ data, bf16* __restrict__ outb,
                    const float* __restrict__ g, const float* __restrict__ b) {
    constexpr int E = W / 128;
    int wid = threadIdx.x >> 5, lane = threadIdx.x & 31;
    size_t row = (size_t)blockIdx.x * 8 + wid;
    float4* p = (float4*)(data + row * W);

    float4 v[E];
    float s = 0.f, s2 = 0.f;
    #pragma unroll
    for (int e = 0; e < E; e++) {
        v[e] = p[lane + e * 32];
        s  += v[e].x + v[e].y + v[e].z + v[e].w;
        s2 += v[e].x * v[e].x + v[e].y * v[e].y + v[e].z * v[e].z + v[e].w * v[e].w;
    }
    #pragma unroll
    for (int o = 16; o > 0; o >>= 1) {
        s  += __shfl_xor_sync(0xffffffffu, s, o);
        s2 += __shfl_xor_sync(0xffffffffu, s2, o);
    }
    float mean = s * (1.f / W);
    float var = s2 * (1.f / W) - mean * mean;
    float inv = rsqrtf(var + LN_EPS);

    #pragma unroll
    for (int e = 0; e < E; e++) {
        int c4 = (lane + e * 32) * 4;
        float4 gg = *(const float4*)(g + c4);
        float4 bb = *(const float4*)(b + c4);
        float4 o;
        o.x = (v[e].x - mean) * inv * gg.x + bb.x;
        o.y = (v[e].y - mean) * inv * gg.y + bb.y;
        o.z = (v[e].z - mean) * inv * gg.z + bb.z;
        o.w = (v[e].w - mean) * inv * gg.w + bb.w;
        if (DOELU) {
            o.x = o.x > 0.f ? o.x : expm1f(o.x);
            o.y = o.y > 0.f ? o.y : expm1f(o.y);
            o.z = o.z > 0.f ? o.z : expm1f(o.z);
            o.w = o.w > 0.f ? o.w : expm1f(o.w);
        }
        if (WF32) p[lane + e * 32] = o;
        if (WB16) {
            bf16* q = outb + row * W + c4;
            *(bf162*)(q)     = __floats2bfloat162_rn(o.x, o.y);
            *(bf162*)(q + 2) = __floats2bfloat162_rn(o.z, o.w);
        }
    }
}

// ---------------------------------------------------------------------------
// Small kernels
// ---------------------------------------------------------------------------
__device__ __forceinline__ int read_t(const void* p) {
    int v = *(const int*)p;
    if (v >= 3 && v < 1000000) return v;
    float f = *(const float*)p;
    return (int)(f + 0.5f);
}

__device__ __forceinline__ float blk_sum(float v, float* red) {
    int tid = threadIdx.x;
    red[tid] = v; __syncthreads();
    #pragma unroll
    for (int s = 128; s > 0; s >>= 1) {
        if (tid < s) red[tid] += red[tid + s];
        __syncthreads();
    }
    float r = red[0]; __syncthreads();
    return r;
}
__device__ __forceinline__ float blk_max(float v, float* red) {
    int tid = threadIdx.x;
    red[tid] = v; __syncthreads();
    #pragma unroll
    for (int s = 128; s > 0; s >>= 1) {
        if (tid < s) red[tid] = fmaxf(red[tid], red[tid + s]);
        __syncthreads();
    }
    float r = red[0]; __syncthreads();
    return r;
}

__global__ void prep_kernel(const void* __restrict__ tptr,
                            const float* __restrict__ query,
                            const float* __restrict__ qkv_w,
                            const float* __restrict__ qkv_b) {
    int t = read_t(tptr);
    if (blockIdx.x == 0) {
        int j = threadIdx.x;
        const float* qrow = query + (size_t)(t - 3) * H_;
        float acc = qkv_b[j];
        #pragma unroll 4
        for (int i = 0; i < H_; i++)
            acc += qrow[i] * qkv_w[(size_t)i * 3 * H_ + j];
        d_qv[j] = acc;
    } else {
        #pragma unroll
        for (int r = 0; r < 2; r++) {
            int i = threadIdx.x + r * 256;
            int half = (i < H_) ? i : (i - H_);
            float fr  = expf(-logf(10000.f) * (float)half / (float)H_);
            float ang = (float)t * fr;
            d_te[i] = (i < H_) ? sinf(ang) : cosf(ang);
        }
    }
}

// Attention over bf16 kv
__global__ __launch_bounds__(256)
void attn_kernel(const bf16* __restrict__ kv) {
    int b = blockIdx.x, h = blockIdx.y;
    __shared__ float lg[N_];
    __shared__ float qs[HD];
    __shared__ float red[256];
    __shared__ float vred[8][HD];

    int tid = threadIdx.x;
    if (tid < HD) qs[tid] = d_qv[h * HD + tid];
    __syncthreads();

    const float scale = rsqrtf((float)HD);
    float lmax = -INFINITY;
    for (int n = tid; n < N_; n += 256) {
        const bf162* kp = (const bf162*)(kv + (size_t)(b * N_ + n) * 2 * H_ + h * HD);
        float dot = 0.f;
        #pragma unroll
        for (int d2 = 0; d2 < HD / 2; d2++) {
            float2 f = __bfloat1622float2(kp[d2]);
            dot += qs[d2 * 2] * f.x + qs[d2 * 2 + 1] * f.y;
        }
        dot *= scale;
        lg[n] = dot;
        lmax = fmaxf(lmax, dot);
    }
    float m = blk_max(lmax, red);

    float lsum = 0.f;
    for (int n = tid; n < N_; n += 256) {
        float p = expf(lg[n] - m);
        lg[n] = p;
        lsum += p;
    }
    float ssum = blk_sum(lsum, red);

    int w = tid >> 5, lane = tid & 31;
    float acc = 0.f;
    for (int n = w; n < N_; n += 8)
        acc += lg[n] * __bfloat162float(
            kv[(size_t)(b * N_ + n) * 2 * H_ + H_ + h * HD + lane]);
    vred[w][lane] = acc;
    __syncthreads();
    if (w == 0) {
        float s = 0.f;
        #pragma unroll
        for (int i = 0; i < 8; i++) s += vred[i][lane];
        d_ctx[b * H_ + h * HD + lane] = s / ssum;
    }
}

__global__ __launch_bounds__(256)
void outproj_kernel(const float* __restrict__ out_w,
                    const float* __restrict__ out_b) {
    int b = blockIdx.x, j = threadIdx.x;
    __shared__ float cs[H_];
    cs[j] = d_ctx[b * H_ + j];
    __syncthreads();
    float acc = out_b[j];
    #pragma unroll 4
    for (int i = 0; i < H_; i++) acc += cs[i] * out_w[(size_t)i * H_ + j];
    d_nf[b * H_ + j] = acc;
}

// e[b,n,:] = concat(new_feat[b], max(x[b,n], x[b,parent])) + te  -> bf16
__global__ __launch_bounds__(128)
void edge_kernel(const float* __restrict__ x, const int* __restrict__ eidx) {
    int row = blockIdx.x;
    int b = row / (N_ - 1), n = row % (N_ - 1);
    int pid = eidx[((size_t)b * N_ + n) * 2];
    int tid = threadIdx.x;

    bf16* ep = d_eb + (size_t)row * 2 * H_ + tid * 4;
    const float4* tep = (const float4*)d_te;
    float4 o;

    if (tid < 64) {
        const float4* nfp = (const float4*)(d_nf + b * H_);
        float4 v = nfp[tid], t4 = tep[tid];
        o = make_float4(v.x + t4.x, v.y + t4.y, v.z + t4.z, v.w + t4.w);
    } else {
        int c = tid - 64;
        const float4* cp = (const float4*)(x + (size_t)(b * N_ + n) * H_);
        const float4* pp = (const float4*)(x + (size_t)(b * N_ + pid) * H_);
        float4 a = cp[c], p = pp[c], t4 = tep[tid];
        o = make_float4(fmaxf(a.x, p.x) + t4.x, fmaxf(a.y, p.y) + t4.y,
                        fmaxf(a.z, p.z) + t4.z, fmaxf(a.w, p.w) + t4.w);
    }
    *(bf162*)(ep)     = __floats2bfloat162_rn(o.x, o.y);
    *(bf162*)(ep + 2) = __floats2bfloat162_rn(o.z, o.w);
}

// logits = h @ r3_w + r3_b   (h in bf16)
__global__ __launch_bounds__(256)
void matvec_kernel(const bf16* __restrict__ h, const float* __restrict__ w,
                   const float* __restrict__ b) {
    __shared__ float ws[512];
    int tid = threadIdx.x;
    ws[tid] = w[tid];
    ws[tid + 256] = w[tid + 256];
    __syncthreads();

    int wid = tid >> 5, lane = tid & 31;
    int row = blockIdx.x * 8 + wid;
    const bf162* p = (const bf162*)(h + (size_t)row * 512);
    float s = 0.f;
    #pragma unroll
    for (int i = 0; i < 8; i++) {
        int kp = lane + i * 32;
        float2 f = __bfloat1622float2(p[kp]);
        s += f.x * ws[kp * 2] + f.y * ws[kp * 2 + 1];
    }
    #pragma unroll
    for (int o = 16; o > 0; o >>= 1) s += __shfl_down_sync(0xffffffffu, s, o);
    if (lane == 0) d_lg[row] = s + b[0];
}

__global__ __launch_bounds__(256)
void lsm_kernel(float* __restrict__ out) {
    int b = blockIdx.x, tid = threadIdx.x;
    const int L = N_ - 1;
    const float* p = d_lg + (size_t)b * L;
    __shared__ float red[256];

    float m = -INFINITY;
    for (int n = tid; n < L; n += 256) m = fmaxf(m, p[n]);
    float mm = blk_max(m, red);

    float s = 0.f;
    for (int n = tid; n < L; n += 256) s += expf(p[n] - mm);
    float ls = mm + logf(blk_sum(s, red));

    for (int n = tid; n < L; n += 256)
        out[(size_t)b * L + n] = p[n] - ls;
}

// ---------------------------------------------------------------------------
// kernel_launch
// ---------------------------------------------------------------------------
extern "C" void kernel_launch(void* const* d_in, const int* in_sizes, int n_in,
                              void* d_out, int out_size) {
    const float* nf_in  = (const float*)d_in[0];
    const int*   eidx   = (const int*)  d_in[1];
    const void*  tptr   =               d_in[2];
    const float* query  = (const float*)d_in[3];
    const float* mlp_w1 = (const float*)d_in[4];
    const float* mlp_b1 = (const float*)d_in[5];
    const float* mlp_w2 = (const float*)d_in[6];
    const float* mlp_b2 = (const float*)d_in[7];
    const float* mlp_g  = (const float*)d_in[8];
    const float* mlp_b  = (const float*)d_in[9];
    const float* qkv_w  = (const float*)d_in[10];
    const float* qkv_b  = (const float*)d_in[11];
    const float* out_w  = (const float*)d_in[12];
    const float* out_b  = (const float*)d_in[13];
    const float* r1_w   = (const float*)d_in[14];
    const float* r1_b   = (const float*)d_in[15];
    const float* r1_g   = (const float*)d_in[16];
    const float* r1_bb  = (const float*)d_in[17];
    const float* r2_w   = (const float*)d_in[18];
    const float* r2_b   = (const float*)d_in[19];
    const float* r2_g   = (const float*)d_in[20];
    const float* r2_bb  = (const float*)d_in[21];
    const float* r3_w   = (const float*)d_in[22];
    const float* r3_b   = (const float*)d_in[23];
    float* out = (float*)d_out;

    float *p_x, *p_h;
    bf16 *p_nfb, *p_t1b, *p_xb, *p_kvb, *p_eb, *p_hb;
    bf16 *p_w1t, *p_w2t, *p_kvwt, *p_r1wt, *p_r2wt;
    cudaGetSymbolAddress((void**)&p_x,   d_x);
    cudaGetSymbolAddress((void**)&p_h,   d_h);
    cudaGetSymbolAddress((void**)&p_nfb, d_nfb);
    cudaGetSymbolAddress((void**)&p_t1b, d_t1b);
    cudaGetSymbolAddress((void**)&p_xb,  d_xb);
    cudaGetSymbolAddress((void**)&p_kvb, d_kvb);
    cudaGetSymbolAddress((void**)&p_eb,  d_eb);
    cudaGetSymbolAddress((void**)&p_hb,  d_hb);
    cudaGetSymbolAddress((void**)&p_w1t,  d_w1t);
    cudaGetSymbolAddress((void**)&p_w2t,  d_w2t);
    cudaGetSymbolAddress((void**)&p_kvwt, d_kvwt);
    cudaGetSymbolAddress((void**)&p_r1wt, d_r1wt);
    cudaGetSymbolAddress((void**)&p_r2wt, d_r2wt);

    cudaFuncSetAttribute(tc_gemm_kernel<1, false, true>,
                         cudaFuncAttributeMaxDynamicSharedMemorySize, GEMM_SMEM);
    cudaFuncSetAttribute(tc_gemm_kernel<0, true, false>,
                         cudaFuncAttributeMaxDynamicSharedMemorySize, GEMM_SMEM);
    cudaFuncSetAttribute(tc_gemm_kernel<0, false, true>,
                         cudaFuncAttributeMaxDynamicSharedMemorySize, GEMM_SMEM);

    // Weight transposes -> bf16 [N][K]
    transpose_kernel<<<dim3(NTIPS / 32, H_ / 32), 256>>>(mlp_w1, p_w1t, NTIPS, H_, H_);
    transpose_kernel<<<dim3(H_ / 32, H_ / 32), 256>>>(mlp_w2, p_w2t, H_, H_, H_);
    transpose_kernel<<<dim3(H_ / 32, 2 * H_ / 32), 256>>>(qkv_w + H_, p_kvwt, H_, 2 * H_, 3 * H_);
    transpose_kernel<<<dim3(2 * H_ / 32, 2 * H_ / 32), 256>>>(r1_w, p_r1wt, 2 * H_, 2 * H_, 2 * H_);
    transpose_kernel<<<dim3(2 * H_ / 32, 2 * H_ / 32), 256>>>(r2_w, p_r2wt, 2 * H_, 2 * H_, 2 * H_);

    // node_features -> bf16
    cvt_kernel<<<(size_t)M1 * NTIPS / 1024, 256>>>(nf_in, p_nfb);

    // Stage 1: MLP
    tc_gemm_kernel<1, false, true><<<dim3(H_ / 128, M1 / 128), 256, GEMM_SMEM>>>(
        p_nfb, p_w1t, mlp_b1, nullptr, p_t1b, M1, H_, NTIPS);
    tc_gemm_kernel<0, true, false><<<dim3(H_ / 128, M1 / 128), 256, GEMM_SMEM>>>(
        p_t1b, p_w2t, mlp_b2, p_x, nullptr, M1, H_, H_);
    ln_warp_kernel<H_, false, true, true><<<M1 / 8, 256>>>(p_x, p_xb, mlp_g, mlp_b);

    // q vector + time embedding
    prep_kernel<<<2, 256>>>(tptr, query, qkv_w, qkv_b);

    // kv projection -> bf16
    tc_gemm_kernel<0, false, true><<<dim3(2 * H_ / 128, M1 / 128), 256, GEMM_SMEM>>>(
        p_xb, p_kvwt, qkv_b + H_, nullptr, p_kvb, M1, 2 * H_, H_);

    // Attention + output projection
    attn_kernel<<<dim3(B_, NH), 256>>>(p_kvb);
    outproj_kernel<<<B_, 256>>>(out_w, out_b);

    // Edge features + time embedding -> bf16
    edge_kernel<<<M2, 128>>>(p_x, eidx);

    // Readout stack
    tc_gemm_kernel<0, true, false><<<dim3(2 * H_ / 128, M2 / 128), 256, GEMM_SMEM>>>(
        p_eb, p_r1wt, r1_b, p_h, nullptr, M2, 2 * H_, 2 * H_);
    ln_warp_kernel<2 * H_, true, false, true><<<M2 / 8, 256>>>(p_h, p_hb, r1_g, r1_bb);

    tc_gemm_kernel<0, true, false><<<dim3(2 * H_ / 128, M2 / 128), 256, GEMM_SMEM>>>(
        p_hb, p_r2wt, r2_b, p_h, nullptr, M2, 2 * H_, 2 * H_);
    ln_warp_kernel<2 * H_, true, false, true><<<M2 / 8, 256>>>(p_h, p_eb, r2_g, r2_bb);

    matvec_kernel<<<M2 / 8, 256>>>(p_eb, r3_w, r3_b);
    lsm_kernel<<<B_, 256>>>(out);
}

// round 13
// speedup vs baseline: 1.0109x; 1.0109x over previous
#include <cuda_runtime.h>
#include <cuda_bf16.h>
#include <math.h>
#include <stdint.h>

// ---------------------------------------------------------------------------
// Problem constants (fixed shapes)
// ---------------------------------------------------------------------------
#define B_    128
#define N_    1022
#define NTIPS 512
#define H_    256
#define NH    8
#define HD    32
#define M1    (B_ * N_)        // 130816
#define M2    (B_ * (N_ - 1)) // 130688
#define LN_EPS 1e-5f

typedef __nv_bfloat16  bf16;
typedef __nv_bfloat162 bf162;

// ---------------------------------------------------------------------------
// Scratch (static device globals)
// ---------------------------------------------------------------------------
__device__ bf16  d_nfb[(size_t)M1 * NTIPS];     // node_features in bf16
__device__ bf16  d_t1b[(size_t)M1 * H_];        // elu(nf@w1+b1) bf16
__device__ float d_x  [(size_t)M1 * H_];        // ln(..) fp32 (edge reads)
__device__ bf16  d_xb [(size_t)M1 * H_];        // ln(..) bf16 (kv gemm A)
__device__ bf16  d_kvb[(size_t)M1 * 2 * H_];    // kv bf16 (attn reads)
__device__ bf16  d_eb [(size_t)M2 * 2 * H_];    // edge feats bf16 (r1 A); reused for e2b
__device__ float d_h  [(size_t)M2 * 2 * H_];    // r1 out fp32; reused for r2 out
__device__ bf16  d_hb [(size_t)M2 * 2 * H_];    // ln(elu(r1)) bf16 (r2 A)
__device__ float d_qv [H_];
__device__ float d_te [2 * H_];
__device__ float d_ctx[B_ * H_];
__device__ float d_nf [B_ * H_];
__device__ float d_lg [M2];
// transposed bf16 weights ([N][K], K contiguous)
__device__ bf16 d_w1t [H_ * NTIPS];
__device__ bf16 d_w2t [H_ * H_];
__device__ bf16 d_kvwt[2 * H_ * H_];
__device__ bf16 d_r1wt[2 * H_ * 2 * H_];
__device__ bf16 d_r2wt[2 * H_ * 2 * H_];

// ---------------------------------------------------------------------------
// helpers
// ---------------------------------------------------------------------------
__device__ __forceinline__ uint32_t smem_u32(const void* p) {
    uint32_t a;
    asm("{ .reg .u64 t; cvta.to.shared.u64 t, %1; cvt.u32.u64 %0, t; }"
        : "=r"(a) : "l"(p));
    return a;
}

__device__ __forceinline__ void mma_bf16(float* c, const uint32_t* a,
                                         const uint32_t* b) {
    asm volatile(
        "mma.sync.aligned.m16n8k16.row.col.f32.bf16.bf16.f32 "
        "{%0,%1,%2,%3}, {%4,%5,%6,%7}, {%8,%9}, {%0,%1,%2,%3};"
        : "+f"(c[0]), "+f"(c[1]), "+f"(c[2]), "+f"(c[3])
        : "r"(a[0]), "r"(a[1]), "r"(a[2]), "r"(a[3]), "r"(b[0]), "r"(b[1]));
}

__device__ __forceinline__ void ldsm_x4(uint32_t& r0, uint32_t& r1,
                                        uint32_t& r2, uint32_t& r3,
                                        uint32_t addr) {
    asm volatile(
        "ldmatrix.sync.aligned.m8n8.x4.shared.b16 {%0,%1,%2,%3}, [%4];"
        : "=r"(r0), "=r"(r1), "=r"(r2), "=r"(r3) : "r"(addr));
}

#define CP_ASYNC16(dst, src) \
    asm volatile("cp.async.cg.shared.global [%0], [%1], 16;" \
        :: "r"(dst), "l"(src) : "memory")
#define CP_COMMIT() asm volatile("cp.async.commit_group;" ::: "memory")
#define CP_WAIT1()  asm volatile("cp.async.wait_group 1;" ::: "memory")
#define CP_WAIT0()  asm volatile("cp.async.wait_group 0;" ::: "memory")

// ---------------------------------------------------------------------------
// bf16 tensor-core GEMM: C[M,Nn] = act(A[M,K] @ Bt[Nn,K]^T + bias)
// Block tile 128x128, BK=64, 256 threads (8 warps, 2m x 4n), warp 64x32,
// mma.m16n8k16.bf16 with ldmatrix.x4 fragment loads.
// 2-stage cp.async pipeline, 2 CTAs/SM.
// SMEM per stage: A,B each [128][36] u32 (32 data + 4 pad);
// row stride 36 u32 -> 9 16B-groups mod 8 distinct over 8 rows: LDSM
// phases and cp.async writes conflict-free.
// ---------------------------------------------------------------------------
#define BKC 64
#define LDS_STR 36
#define TILE_U32 (128 * LDS_STR)                 // 4608
#define GEMM_SMEM (2 * 2 * TILE_U32 * 4)         // 73728 bytes

template <int ACT, bool WF32, bool WB16>  // ACT: 0 none, 1 elu
__global__ __launch_bounds__(256, 2)
void tc_gemm_kernel(const bf16* __restrict__ A, const bf16* __restrict__ Bt,
                    const float* __restrict__ bias,
                    float* __restrict__ Cf, bf16* __restrict__ Cb,
                    int M, int Nn, int K) {
    extern __shared__ uint32_t smem[];

    const int tid = threadIdx.x;
    const int bn = blockIdx.x, bm = blockIdx.y;

    // copy mapping: row = tid>>1 (0..127), 4x16B segs at (tid&1)*64 bytes
    const int crow = tid >> 1;
    const int chalf = tid & 1;
    const bf16* Ag = A + (size_t)(bm * 128 + crow) * K + chalf * 32;
    const bf16* Bg = Bt + (size_t)(bn * 128 + crow) * K + chalf * 32;

    const uint32_t sbase = smem_u32(smem);
    const uint32_t cbyte = (uint32_t)crow * (LDS_STR * 4) + chalf * 64;

    // warp mapping
    const int wid = tid >> 5, lane = tid & 31;
    const int wm = (wid & 1) * 64;
    const int wn = (wid >> 1) * 32;
    const int g = lane >> 2, tig = lane & 3;

    // ldmatrix lane offsets (u32 units within a tile)
    // A tiles per mt: {rows 0-7,c0},{rows 8-15,c0},{rows 0-7,c4},{rows 8-15,c4}
    const int tgrp = lane >> 3;
    const uint32_t aoff = ((lane & 7) + ((tgrp & 1) * 8)) * LDS_STR + (tgrp >> 1) * 4;
    // B tiles per nt-pair: {nt,c0},{nt,c4},{nt+1,c0},{nt+1,c4}
    const uint32_t boff = ((lane & 7) + ((tgrp >> 1) * 8)) * LDS_STR + (tgrp & 1) * 4;

    float c[4][4][4];
    #pragma unroll
    for (int mt = 0; mt < 4; mt++)
        #pragma unroll
        for (int nt = 0; nt < 4; nt++)
            #pragma unroll
            for (int i = 0; i < 4; i++) c[mt][nt][i] = 0.f;

    const int NC = K >> 6;   // 4 or 8

    // prologue: copy stage 0
    {
        const uint32_t ad = sbase + cbyte;
        const uint32_t bd = ad + TILE_U32 * 4;
        #pragma unroll
        for (int i = 0; i < 4; i++) {
            CP_ASYNC16(ad + i * 16, Ag + i * 8);
            CP_ASYNC16(bd + i * 16, Bg + i * 8);
        }
        CP_COMMIT();
    }

    for (int kc = 0; kc < NC; kc++) {
        const int cur = kc & 1;

        __syncthreads();  // all warps done reading buffer cur^1 before overwrite
        if (kc + 1 < NC) {
            const uint32_t ad = sbase + (uint32_t)(cur ^ 1) * 2 * TILE_U32 * 4 + cbyte;
            const uint32_t bd = ad + TILE_U32 * 4;
            const bf16* as = Ag + (kc + 1) * BKC;
            const bf16* bs = Bg + (kc + 1) * BKC;
            #pragma unroll
            for (int i = 0; i < 4; i++) {
                CP_ASYNC16(ad + i * 16, as + i * 8);
                CP_ASYNC16(bd + i * 16, bs + i * 8);
            }
            CP_COMMIT();
            CP_WAIT1();
        } else {
            CP_WAIT0();
        }
        __syncthreads();

        const uint32_t Abase = sbase + (uint32_t)cur * 2 * TILE_U32 * 4;
        const uint32_t Bbase = Abase + TILE_U32 * 4;
        #pragma unroll
        for (int ks = 0; ks < 4; ks++) {      // four k16 steps per BK=64
            const int p0 = ks * 8;
            uint32_t a[4][4], b[8];
            #pragma unroll
            for (int mt = 0; mt < 4; mt++) {
                uint32_t addr = Abase +
                    (((uint32_t)(wm + mt * 16) * LDS_STR + p0 + aoff) << 2);
                ldsm_x4(a[mt][0], a[mt][1], a[mt][2], a[mt][3], addr);
            }
            #pragma unroll
            for (int np = 0; np < 2; np++) {
                uint32_t addr = Bbase +
                    (((uint32_t)(wn + np * 16) * LDS_STR + p0 + boff) << 2);
                ldsm_x4(b[np * 4 + 0], b[np * 4 + 1],
                        b[np * 4 + 2], b[np * 4 + 3], addr);
            }
            #pragma unroll
            for (int mt = 0; mt < 4; mt++)
                #pragma unroll
                for (int nt = 0; nt < 4; nt++)
                    mma_bf16(c[mt][nt], a[mt], b + nt * 2);
        }
    }

    // Epilogue: bias + optional ELU; fp32 and/or bf16 stores
    #pragma unroll
    for (int mt = 0; mt < 4; mt++) {
        #pragma unroll
        for (int nt = 0; nt < 4; nt++) {
            int col = bn * 128 + wn + nt * 8 + 2 * tig;
            float b0 = __ldg(bias + col), b1 = __ldg(bias + col + 1);
            #pragma unroll
            for (int half = 0; half < 2; half++) {
                int row = bm * 128 + wm + mt * 16 + g + half * 8;
                float v0 = c[mt][nt][half * 2 + 0] + b0;
                float v1 = c[mt][nt][half * 2 + 1] + b1;
                if (ACT == 1) {
                    v0 = v0 > 0.f ? v0 : expm1f(v0);
                    v1 = v1 > 0.f ? v1 : expm1f(v1);
                }
                if (WF32)
                    *(float2*)(Cf + (size_t)row * Nn + col) = make_float2(v0, v1);
                if (WB16)
                    *(bf162*)(Cb + (size_t)row * Nn + col) =
                        __floats2bfloat162_rn(v0, v1);
            }
        }
    }
}

// ---------------------------------------------------------------------------
// Weight transpose to bf16: out[n*K+k] = bf16(in[k*ldin + n])
// ---------------------------------------------------------------------------
__global__ __launch_bounds__(256)
void transpose_kernel(const float* __restrict__ in, bf16* __restrict__ out,
                      int K, int N, int ldin) {
    __shared__ float tile[32][33];
    int k0 = blockIdx.x * 32, n0 = blockIdx.y * 32;
    int x = threadIdx.x & 31, y = (threadIdx.x >> 5) * 4;
    #pragma unroll
    for (int i = 0; i < 4; i++)
        tile[y + i][x] = in[(size_t)(k0 + y + i) * ldin + n0 + x];
    __syncthreads();
    #pragma unroll
    for (int i = 0; i < 4; i++)
        out[(size_t)(n0 + y + i) * K + k0 + x] =
            __float2bfloat16_rn(tile[x][y + i]);
}

// ---------------------------------------------------------------------------
// fp32 -> bf16 elementwise convert (for node_features)
// ---------------------------------------------------------------------------
__global__ __launch_bounds__(256)
void cvt_kernel(const float* __restrict__ in, bf16* __restrict__ out) {
    size_t i = ((size_t)blockIdx.x * 256 + threadIdx.x) * 4;
    float4 v = *(const float4*)(in + i);
    *(bf162*)(out + i)     = __floats2bfloat162_rn(v.x, v.y);
    *(bf162*)(out + i + 2) = __floats2bfloat162_rn(v.z, v.w);
}

// ---------------------------------------------------------------------------
// Warp-per-row LayerNorm, optional ELU; fp32 in-place and/or bf16 copy out.
// 8 rows / block.
// ---------------------------------------------------------------------------
template <int W, bool DOELU, bool WF32, bool WB16>
__global__ __launch_bounds__(256)
void ln_warp_kernel(float* __restrict__ data, bf16* __restrict__ outb,
                    const float* __restrict__ g, const float* __restrict__ b) {
    constexpr int E = W / 128;
    int wid = threadIdx.x >> 5, lane = threadIdx.x & 31;
    size_t row = (size_t)blockIdx.x * 8 + wid;
    float4* p = (float4*)(data + row * W);

    float4 v[E];
    float s = 0.f, s2 = 0.f;
    #pragma unroll
    for (int e = 0; e < E; e++) {
        v[e] = p[lane + e * 32];
        s  += v[e].x + v[e].y + v[e].z + v[e].w;
        s2 += v[e].x * v[e].x + v[e].y * v[e].y + v[e].z * v[e].z + v[e].w * v[e].w;
    }
    #pragma unroll
    for (int o = 16; o > 0; o >>= 1) {
        s  += __shfl_xor_sync(0xffffffffu, s, o);
        s2 += __shfl_xor_sync(0xffffffffu, s2, o);
    }
    float mean = s * (1.f / W);
    float var = s2 * (1.f / W) - mean * mean;
    float inv = rsqrtf(var + LN_EPS);

    #pragma unroll
    for (int e = 0; e < E; e++) {
        int c4 = (lane + e * 32) * 4;
        float4 gg = *(const float4*)(g + c4);
        float4 bb = *(const float4*)(b + c4);
        float4 o;
        o.x = (v[e].x - mean) * inv * gg.x + bb.x;
        o.y = (v[e].y - mean) * inv * gg.y + bb.y;
        o.z = (v[e].z - mean) * inv * gg.z + bb.z;
        o.w = (v[e].w - mean) * inv * gg.w + bb.w;
        if (DOELU) {
            o.x = o.x > 0.f ? o.x : expm1f(o.x);
            o.y = o.y > 0.f ? o.y : expm1f(o.y);
            o.z = o.z > 0.f ? o.z : expm1f(o.z);
            o.w = o.w > 0.f ? o.w : expm1f(o.w);
        }
        if (WF32) p[lane + e * 32] = o;
        if (WB16) {
            bf16* q = outb + row * W + c4;
            *(bf162*)(q)     = __floats2bfloat162_rn(o.x, o.y);
            *(bf162*)(q + 2) = __floats2bfloat162_rn(o.z, o.w);
        }
    }
}

// ---------------------------------------------------------------------------
// Small kernels
// ---------------------------------------------------------------------------
__device__ __forceinline__ int read_t(const void* p) {
    int v = *(const int*)p;
    if (v >= 3 && v < 1000000) return v;
    float f = *(const float*)p;
    return (int)(f + 0.5f);
}

__device__ __forceinline__ float blk_sum(float v, float* red) {
    int tid = threadIdx.x;
    red[tid] = v; __syncthreads();
    #pragma unroll
    for (int s = 128; s > 0; s >>= 1) {
        if (tid < s) red[tid] += red[tid + s];
        __syncthreads();
    }
    float r = red[0]; __syncthreads();
    return r;
}
__device__ __forceinline__ float blk_max(float v, float* red) {
    int tid = threadIdx.x;
    red[tid] = v; __syncthreads();
    #pragma unroll
    for (int s = 128; s > 0; s >>= 1) {
        if (tid < s) red[tid] = fmaxf(red[tid], red[tid + s]);
        __syncthreads();
    }
    float r = red[0]; __syncthreads();
    return r;
}

__global__ void prep_kernel(const void* __restrict__ tptr,
                            const float* __restrict__ query,
                            const float* __restrict__ qkv_w,
                            const float* __restrict__ qkv_b) {
    int t = read_t(tptr);
    if (blockIdx.x == 0) {
        int j = threadIdx.x;
        const float* qrow = query + (size_t)(t - 3) * H_;
        float acc = qkv_b[j];
        #pragma unroll 4
        for (int i = 0; i < H_; i++)
            acc += qrow[i] * qkv_w[(size_t)i * 3 * H_ + j];
        d_qv[j] = acc;
    } else {
        #pragma unroll
        for (int r = 0; r < 2; r++) {
            int i = threadIdx.x + r * 256;
            int half = (i < H_) ? i : (i - H_);
            float fr  = expf(-logf(10000.f) * (float)half / (float)H_);
            float ang = (float)t * fr;
            d_te[i] = (i < H_) ? sinf(ang) : cosf(ang);
        }
    }
}

// Attention over bf16 kv
__global__ __launch_bounds__(256)
void attn_kernel(const bf16* __restrict__ kv) {
    int b = blockIdx.x, h = blockIdx.y;
    __shared__ float lg[N_];
    __shared__ float qs[HD];
    __shared__ float red[256];
    __shared__ float vred[8][HD];

    int tid = threadIdx.x;
    if (tid < HD) qs[tid] = d_qv[h * HD + tid];
    __syncthreads();

    const float scale = rsqrtf((float)HD);
    float lmax = -INFINITY;
    for (int n = tid; n < N_; n += 256) {
        const bf162* kp = (const bf162*)(kv + (size_t)(b * N_ + n) * 2 * H_ + h * HD);
        float dot = 0.f;
        #pragma unroll
        for (int d2 = 0; d2 < HD / 2; d2++) {
            float2 f = __bfloat1622float2(kp[d2]);
            dot += qs[d2 * 2] * f.x + qs[d2 * 2 + 1] * f.y;
        }
        dot *= scale;
        lg[n] = dot;
        lmax = fmaxf(lmax, dot);
    }
    float m = blk_max(lmax, red);

    float lsum = 0.f;
    for (int n = tid; n < N_; n += 256) {
        float p = expf(lg[n] - m);
        lg[n] = p;
        lsum += p;
    }
    float ssum = blk_sum(lsum, red);

    int w = tid >> 5, lane = tid & 31;
    float acc = 0.f;
    for (int n = w; n < N_; n += 8)
        acc += lg[n] * __bfloat162float(
            kv[(size_t)(b * N_ + n) * 2 * H_ + H_ + h * HD + lane]);
    vred[w][lane] = acc;
    __syncthreads();
    if (w == 0) {
        float s = 0.f;
        #pragma unroll
        for (int i = 0; i < 8; i++) s += vred[i][lane];
        d_ctx[b * H_ + h * HD + lane] = s / ssum;
    }
}

__global__ __launch_bounds__(256)
void outproj_kernel(const float* __restrict__ out_w,
                    const float* __restrict__ out_b) {
    int b = blockIdx.x, j = threadIdx.x;
    __shared__ float cs[H_];
    cs[j] = d_ctx[b * H_ + j];
    __syncthreads();
    float acc = out_b[j];
    #pragma unroll 4
    for (int i = 0; i < H_; i++) acc += cs[i] * out_w[(size_t)i * H_ + j];
    d_nf[b * H_ + j] = acc;
}

// e[b,n,:] = concat(new_feat[b], max(x[b,n], x[b,parent])) + te  -> bf16
__global__ __launch_bounds__(128)
void edge_kernel(const float* __restrict__ x, const int* __restrict__ eidx) {
    int row = blockIdx.x;
    int b = row / (N_ - 1), n = row % (N_ - 1);
    int pid = eidx[((size_t)b * N_ + n) * 2];
    int tid = threadIdx.x;

    bf16* ep = d_eb + (size_t)row * 2 * H_ + tid * 4;
    const float4* tep = (const float4*)d_te;
    float4 o;

    if (tid < 64) {
        const float4* nfp = (const float4*)(d_nf + b * H_);
        float4 v = nfp[tid], t4 = tep[tid];
        o = make_float4(v.x + t4.x, v.y + t4.y, v.z + t4.z, v.w + t4.w);
    } else {
        int c = tid - 64;
        const float4* cp = (const float4*)(x + (size_t)(b * N_ + n) * H_);
        const float4* pp = (const float4*)(x + (size_t)(b * N_ + pid) * H_);
        float4 a = cp[c], p = pp[c], t4 = tep[tid];
        o = make_float4(fmaxf(a.x, p.x) + t4.x, fmaxf(a.y, p.y) + t4.y,
                        fmaxf(a.z, p.z) + t4.z, fmaxf(a.w, p.w) + t4.w);
    }
    *(bf162*)(ep)     = __floats2bfloat162_rn(o.x, o.y);
    *(bf162*)(ep + 2) = __floats2bfloat162_rn(o.z, o.w);
}

// logits = h @ r3_w + r3_b   (h in bf16)
__global__ __launch_bounds__(256)
void matvec_kernel(const bf16* __restrict__ h, const float* __restrict__ w,
                   const float* __restrict__ b) {
    __shared__ float ws[512];
    int tid = threadIdx.x;
    ws[tid] = w[tid];
    ws[tid + 256] = w[tid + 256];
    __syncthreads();

    int wid = tid >> 5, lane = tid & 31;
    int row = blockIdx.x * 8 + wid;
    const bf162* p = (const bf162*)(h + (size_t)row * 512);
    float s = 0.f;
    #pragma unroll
    for (int i = 0; i < 8; i++) {
        int kp = lane + i * 32;
        float2 f = __bfloat1622float2(p[kp]);
        s += f.x * ws[kp * 2] + f.y * ws[kp * 2 + 1];
    }
    #pragma unroll
    for (int o = 16; o > 0; o >>= 1) s += __shfl_down_sync(0xffffffffu, s, o);
    if (lane == 0) d_lg[row] = s + b[0];
}

__global__ __launch_bounds__(256)
void lsm_kernel(float* __restrict__ out) {
    int b = blockIdx.x, tid = threadIdx.x;
    const int L = N_ - 1;
    const float* p = d_lg + (size_t)b * L;
    __shared__ float red[256];

    float m = -INFINITY;
    for (int n = tid; n < L; n += 256) m = fmaxf(m, p[n]);
    float mm = blk_max(m, red);

    float s = 0.f;
    for (int n = tid; n < L; n += 256) s += expf(p[n] - mm);
    float ls = mm + logf(blk_sum(s, red));

    for (int n = tid; n < L; n += 256)
        out[(size_t)b * L + n] = p[n] - ls;
}

// ---------------------------------------------------------------------------
// kernel_launch
// ---------------------------------------------------------------------------
extern "C" void kernel_launch(void* const* d_in, const int* in_sizes, int n_in,
                              void* d_out, int out_size) {
    const float* nf_in  = (const float*)d_in[0];
    const int*   eidx   = (const int*)  d_in[1];
    const void*  tptr   =               d_in[2];
    const float* query  = (const float*)d_in[3];
    const float* mlp_w1 = (const float*)d_in[4];
    const float* mlp_b1 = (const float*)d_in[5];
    const float* mlp_w2 = (const float*)d_in[6];
    const float* mlp_b2 = (const float*)d_in[7];
    const float* mlp_g  = (const float*)d_in[8];
    const float* mlp_b  = (const float*)d_in[9];
    const float* qkv_w  = (const float*)d_in[10];
    const float* qkv_b  = (const float*)d_in[11];
    const float* out_w  = (const float*)d_in[12];
    const float* out_b  = (const float*)d_in[13];
    const float* r1_w   = (const float*)d_in[14];
    const float* r1_b   = (const float*)d_in[15];
    const float* r1_g   = (const float*)d_in[16];
    const float* r1_bb  = (const float*)d_in[17];
    const float* r2_w   = (const float*)d_in[18];
    const float* r2_b   = (const float*)d_in[19];
    const float* r2_g   = (const float*)d_in[20];
    const float* r2_bb  = (const float*)d_in[21];
    const float* r3_w   = (const float*)d_in[22];
    const float* r3_b   = (const float*)d_in[23];
    float* out = (float*)d_out;

    float *p_x, *p_h;
    bf16 *p_nfb, *p_t1b, *p_xb, *p_kvb, *p_eb, *p_hb;
    bf16 *p_w1t, *p_w2t, *p_kvwt, *p_r1wt, *p_r2wt;
    cudaGetSymbolAddress((void**)&p_x,   d_x);
    cudaGetSymbolAddress((void**)&p_h,   d_h);
    cudaGetSymbolAddress((void**)&p_nfb, d_nfb);
    cudaGetSymbolAddress((void**)&p_t1b, d_t1b);
    cudaGetSymbolAddress((void**)&p_xb,  d_xb);
    cudaGetSymbolAddress((void**)&p_kvb, d_kvb);
    cudaGetSymbolAddress((void**)&p_eb,  d_eb);
    cudaGetSymbolAddress((void**)&p_hb,  d_hb);
    cudaGetSymbolAddress((void**)&p_w1t,  d_w1t);
    cudaGetSymbolAddress((void**)&p_w2t,  d_w2t);
    cudaGetSymbolAddress((void**)&p_kvwt, d_kvwt);
    cudaGetSymbolAddress((void**)&p_r1wt, d_r1wt);
    cudaGetSymbolAddress((void**)&p_r2wt, d_r2wt);

    cudaFuncSetAttribute(tc_gemm_kernel<1, false, true>,
                         cudaFuncAttributeMaxDynamicSharedMemorySize, GEMM_SMEM);
    cudaFuncSetAttribute(tc_gemm_kernel<0, true, false>,
                         cudaFuncAttributeMaxDynamicSharedMemorySize, GEMM_SMEM);
    cudaFuncSetAttribute(tc_gemm_kernel<0, false, true>,
                         cudaFuncAttributeMaxDynamicSharedMemorySize, GEMM_SMEM);

    // Weight transposes -> bf16 [N][K]
    transpose_kernel<<<dim3(NTIPS / 32, H_ / 32), 256>>>(mlp_w1, p_w1t, NTIPS, H_, H_);
    transpose_kernel<<<dim3(H_ / 32, H_ / 32), 256>>>(mlp_w2, p_w2t, H_, H_, H_);
    transpose_kernel<<<dim3(H_ / 32, 2 * H_ / 32), 256>>>(qkv_w + H_, p_kvwt, H_, 2 * H_, 3 * H_);
    transpose_kernel<<<dim3(2 * H_ / 32, 2 * H_ / 32), 256>>>(r1_w, p_r1wt, 2 * H_, 2 * H_, 2 * H_);
    transpose_kernel<<<dim3(2 * H_ / 32, 2 * H_ / 32), 256>>>(r2_w, p_r2wt, 2 * H_, 2 * H_, 2 * H_);

    // node_features -> bf16
    cvt_kernel<<<(size_t)M1 * NTIPS / 1024, 256>>>(nf_in, p_nfb);

    // Stage 1: MLP
    tc_gemm_kernel<1, false, true><<<dim3(H_ / 128, M1 / 128), 256, GEMM_SMEM>>>(
        p_nfb, p_w1t, mlp_b1, nullptr, p_t1b, M1, H_, NTIPS);
    tc_gemm_kernel<0, true, false><<<dim3(H_ / 128, M1 / 128), 256, GEMM_SMEM>>>(
        p_t1b, p_w2t, mlp_b2, p_x, nullptr, M1, H_, H_);
    ln_warp_kernel<H_, false, true, true><<<M1 / 8, 256>>>(p_x, p_xb, mlp_g, mlp_b);

    // q vector + time embedding
    prep_kernel<<<2, 256>>>(tptr, query, qkv_w, qkv_b);

    // kv projection -> bf16
    tc_gemm_kernel<0, false, true><<<dim3(2 * H_ / 128, M1 / 128), 256, GEMM_SMEM>>>(
        p_xb, p_kvwt, qkv_b + H_, nullptr, p_kvb, M1, 2 * H_, H_);

    // Attention + output projection
    attn_kernel<<<dim3(B_, NH), 256>>>(p_kvb);
    outproj_kernel<<<B_, 256>>>(out_w, out_b);

    // Edge features + time embedding -> bf16
    edge_kernel<<<M2, 128>>>(p_x, eidx);

    // Readout stack
    tc_gemm_kernel<0, true, false><<<dim3(2 * H_ / 128, M2 / 128), 256, GEMM_SMEM>>>(
        p_eb, p_r1wt, r1_b, p_h, nullptr, M2, 2 * H_, 2 * H_);
    ln_warp_kernel<2 * H_, true, false, true><<<M2 / 8, 256>>>(p_h, p_hb, r1_g, r1_bb);

    tc_gemm_kernel<0, true, false><<<dim3(2 * H_ / 128, M2 / 128), 256, GEMM_SMEM>>>(
        p_hb, p_r2wt, r2_b, p_h, nullptr, M2, 2 * H_, 2 * H_);
    ln_warp_kernel<2 * H_, true, false, true><<<M2 / 8, 256>>>(p_h, p_eb, r2_g, r2_bb);

    matvec_kernel<<<M2 / 8, 256>>>(p_eb, r3_w, r3_b);
    lsm_kernel<<<B_, 256>>>(out);
}

// round 15
// speedup vs baseline: 1.0176x; 1.0066x over previous
#include <cuda_runtime.h>
#include <cuda_bf16.h>
#include <math.h>
#include <stdint.h>

// ---------------------------------------------------------------------------
// Problem constants (fixed shapes)
// ---------------------------------------------------------------------------
#define B_    128
#define N_    1022
#define NTIPS 512
#define H_    256
#define NH    8
#define HD    32
#define M1    (B_ * N_)        // 130816
#define M2    (B_ * (N_ - 1)) // 130688
#define LN_EPS 1e-5f

typedef __nv_bfloat16  bf16;
typedef __nv_bfloat162 bf162;

// ---------------------------------------------------------------------------
// Scratch (static device globals) — all large intermediates in bf16
// ---------------------------------------------------------------------------
__device__ bf16  d_nfb[(size_t)M1 * NTIPS];     // node_features bf16
__device__ bf16  d_t1b[(size_t)M1 * H_];        // elu(nf@w1+b1)
__device__ bf16  d_x2b[(size_t)M1 * H_];        // gemm2 out (pre-LN)
__device__ bf16  d_xb [(size_t)M1 * H_];        // ln1 out (kv A, edge reads)
__device__ bf16  d_kvb[(size_t)M1 * 2 * H_];    // kv (attn reads)
__device__ bf16  d_eb [(size_t)M2 * 2 * H_];    // edge feats (r1 A); reused ln3 out
__device__ bf16  d_r1b[(size_t)M2 * 2 * H_];    // r1 out pre-LN; reused r2 out
__device__ bf16  d_hb [(size_t)M2 * 2 * H_];    // ln2 out (r2 A)
__device__ float d_qv [H_];
__device__ float d_te [2 * H_];
__device__ float d_ctx[B_ * H_];
__device__ float d_nf [B_ * H_];
__device__ float d_lg [M2];
// transposed bf16 weights ([N][K], K contiguous)
__device__ bf16 d_w1t [H_ * NTIPS];
__device__ bf16 d_w2t [H_ * H_];
__device__ bf16 d_kvwt[2 * H_ * H_];
__device__ bf16 d_r1wt[2 * H_ * 2 * H_];
__device__ bf16 d_r2wt[2 * H_ * 2 * H_];

// ---------------------------------------------------------------------------
// helpers
// ---------------------------------------------------------------------------
__device__ __forceinline__ uint32_t smem_u32(const void* p) {
    uint32_t a;
    asm("{ .reg .u64 t; cvta.to.shared.u64 t, %1; cvt.u32.u64 %0, t; }"
        : "=r"(a) : "l"(p));
    return a;
}

__device__ __forceinline__ void mma_bf16(float* c, const uint32_t* a,
                                         const uint32_t* b) {
    asm volatile(
        "mma.sync.aligned.m16n8k16.row.col.f32.bf16.bf16.f32 "
        "{%0,%1,%2,%3}, {%4,%5,%6,%7}, {%8,%9}, {%0,%1,%2,%3};"
        : "+f"(c[0]), "+f"(c[1]), "+f"(c[2]), "+f"(c[3])
        : "r"(a[0]), "r"(a[1]), "r"(a[2]), "r"(a[3]), "r"(b[0]), "r"(b[1]));
}

#define CP_ASYNC16(dst, src) \
    asm volatile("cp.async.cg.shared.global [%0], [%1], 16;" \
        :: "r"(dst), "l"(src) : "memory")
#define CP_COMMIT() asm volatile("cp.async.commit_group;" ::: "memory")
#define CP_WAIT1()  asm volatile("cp.async.wait_group 1;" ::: "memory")
#define CP_WAIT0()  asm volatile("cp.async.wait_group 0;" ::: "memory")

// ---------------------------------------------------------------------------
// bf16 tensor-core GEMM (R11-proven config): C = act(A @ Bt^T + bias), bf16 out
// Block tile 128x128, BK=32, 256 threads (8 warps, 2m x 4n), warp 64x32,
// mma.m16n8k16.bf16, scalar LDS frags, 2-stage cp.async, 2 CTAs/SM.
// SMEM per stage: A,B each [128][20] u32 (16 bf16-pairs + 4 pad).
// ---------------------------------------------------------------------------
#define BKC 32
#define LDS_STR 20
#define TILE_U32 (128 * LDS_STR)                 // 2560
#define GEMM_SMEM (2 * 2 * TILE_U32 * 4)         // 40960 bytes

template <int ACT>  // 0 none, 1 elu
__global__ __launch_bounds__(256, 2)
void tc_gemm_kernel(const bf16* __restrict__ A, const bf16* __restrict__ Bt,
                    const float* __restrict__ bias, bf16* __restrict__ C,
                    int M, int Nn, int K) {
    extern __shared__ uint32_t smem[];

    const int tid = threadIdx.x;
    const int bn = blockIdx.x, bm = blockIdx.y;

    // copy mapping: row = tid>>1 (0..127), 2x16B segs at (tid&1)*32 bytes
    const int crow = tid >> 1;
    const int chalf = tid & 1;
    const bf16* Ag = A + (size_t)(bm * 128 + crow) * K + chalf * 16;
    const bf16* Bg = Bt + (size_t)(bn * 128 + crow) * K + chalf * 16;

    const uint32_t sbase = smem_u32(smem);
    const uint32_t cbyte = (uint32_t)(crow * LDS_STR) * 4 + chalf * 32;

    // warp mapping
    const int wid = tid >> 5, lane = tid & 31;
    const int wm = (wid & 1) * 64;
    const int wn = (wid >> 1) * 32;
    const int g = lane >> 2, tig = lane & 3;

    float c[4][4][4];
    #pragma unroll
    for (int mt = 0; mt < 4; mt++)
        #pragma unroll
        for (int nt = 0; nt < 4; nt++)
            #pragma unroll
            for (int i = 0; i < 4; i++) c[mt][nt][i] = 0.f;

    const int NC = K >> 5;

    // prologue: copy stage 0
    {
        const uint32_t ad = sbase + cbyte;
        const uint32_t bd = ad + TILE_U32 * 4;
        CP_ASYNC16(ad,      Ag);
        CP_ASYNC16(ad + 16, Ag + 8);
        CP_ASYNC16(bd,      Bg);
        CP_ASYNC16(bd + 16, Bg + 8);
        CP_COMMIT();
    }

    for (int kc = 0; kc < NC; kc++) {
        const int cur = kc & 1;

        __syncthreads();  // all warps done reading buffer cur^1 before overwrite
        if (kc + 1 < NC) {
            const uint32_t ad = sbase + (uint32_t)(cur ^ 1) * 2 * TILE_U32 * 4 + cbyte;
            const uint32_t bd = ad + TILE_U32 * 4;
            const bf16* as = Ag + (kc + 1) * BKC;
            const bf16* bs = Bg + (kc + 1) * BKC;
            CP_ASYNC16(ad,      as);
            CP_ASYNC16(ad + 16, as + 8);
            CP_ASYNC16(bd,      bs);
            CP_ASYNC16(bd + 16, bs + 8);
            CP_COMMIT();
            CP_WAIT1();
        } else {
            CP_WAIT0();
        }
        __syncthreads();

        const uint32_t* Ab = smem + cur * 2 * TILE_U32;
        const uint32_t* Bb = Ab + TILE_U32;
        #pragma unroll
        for (int ks = 0; ks < 2; ks++) {      // two k16 steps per BK=32
            const int p0 = ks * 8;
            uint32_t a[4][4], b[4][2];
            #pragma unroll
            for (int mt = 0; mt < 4; mt++) {
                int r0 = wm + mt * 16 + g;
                a[mt][0] = Ab[(r0    ) * LDS_STR + p0 + tig];
                a[mt][1] = Ab[(r0 + 8) * LDS_STR + p0 + tig];
                a[mt][2] = Ab[(r0    ) * LDS_STR + p0 + tig + 4];
                a[mt][3] = Ab[(r0 + 8) * LDS_STR + p0 + tig + 4];
            }
            #pragma unroll
            for (int nt = 0; nt < 4; nt++) {
                int n0 = wn + nt * 8 + g;
                b[nt][0] = Bb[n0 * LDS_STR + p0 + tig];
                b[nt][1] = Bb[n0 * LDS_STR + p0 + tig + 4];
            }
            #pragma unroll
            for (int mt = 0; mt < 4; mt++)
                #pragma unroll
                for (int nt = 0; nt < 4; nt++)
                    mma_bf16(c[mt][nt], a[mt], b[nt]);
        }
    }

    // Epilogue: bias + optional ELU; bf16 stores
    #pragma unroll
    for (int mt = 0; mt < 4; mt++) {
        #pragma unroll
        for (int nt = 0; nt < 4; nt++) {
            int col = bn * 128 + wn + nt * 8 + 2 * tig;
            float b0 = __ldg(bias + col), b1 = __ldg(bias + col + 1);
            #pragma unroll
            for (int half = 0; half < 2; half++) {
                int row = bm * 128 + wm + mt * 16 + g + half * 8;
                float v0 = c[mt][nt][half * 2 + 0] + b0;
                float v1 = c[mt][nt][half * 2 + 1] + b1;
                if (ACT == 1) {
                    v0 = v0 > 0.f ? v0 : expm1f(v0);
                    v1 = v1 > 0.f ? v1 : expm1f(v1);
                }
                *(bf162*)(C + (size_t)row * Nn + col) =
                    __floats2bfloat162_rn(v0, v1);
            }
        }
    }
}

// ---------------------------------------------------------------------------
// Weight transpose to bf16: out[n*K+k] = bf16(in[k*ldin + n])
// ---------------------------------------------------------------------------
__global__ __launch_bounds__(256)
void transpose_kernel(const float* __restrict__ in, bf16* __restrict__ out,
                      int K, int N, int ldin) {
    __shared__ float tile[32][33];
    int k0 = blockIdx.x * 32, n0 = blockIdx.y * 32;
    int x = threadIdx.x & 31, y = (threadIdx.x >> 5) * 4;
    #pragma unroll
    for (int i = 0; i < 4; i++)
        tile[y + i][x] = in[(size_t)(k0 + y + i) * ldin + n0 + x];
    __syncthreads();
    #pragma unroll
    for (int i = 0; i < 4; i++)
        out[(size_t)(n0 + y + i) * K + k0 + x] =
            __float2bfloat16_rn(tile[x][y + i]);
}

// ---------------------------------------------------------------------------
// fp32 -> bf16 elementwise convert (for node_features)
// ---------------------------------------------------------------------------
__global__ __launch_bounds__(256)
void cvt_kernel(const float* __restrict__ in, bf16* __restrict__ out) {
    size_t i = ((size_t)blockIdx.x * 256 + threadIdx.x) * 4;
    float4 v = *(const float4*)(in + i);
    *(bf162*)(out + i)     = __floats2bfloat162_rn(v.x, v.y);
    *(bf162*)(out + i + 2) = __floats2bfloat162_rn(v.z, v.w);
}

// ---------------------------------------------------------------------------
// Warp-per-row LayerNorm: bf16 in -> bf16 out, optional fused ELU.
// 8 rows / block. Lane handles E = W/128 uint2 chunks (4 bf16 each).
// ---------------------------------------------------------------------------
template <int W, bool DOELU>
__global__ __launch_bounds__(256)
void ln_bf16_kernel(const bf16* __restrict__ in, bf16* __restrict__ outb,
                    const float* __restrict__ g, const float* __restrict__ b) {
    constexpr int E = W / 128;
    int wid = threadIdx.x >> 5, lane = threadIdx.x & 31;
    size_t row = (size_t)blockIdx.x * 8 + wid;
    const uint2* pin = (const uint2*)(in + row * W);

    float4 v[E];
    float s = 0.f, s2 = 0.f;
    #pragma unroll
    for (int e = 0; e < E; e++) {
        uint2 u = pin[lane + e * 32];
        float2 lo = __bfloat1622float2(*(bf162*)&u.x);
        float2 hi = __bfloat1622float2(*(bf162*)&u.y);
        v[e] = make_float4(lo.x, lo.y, hi.x, hi.y);
        s  += v[e].x + v[e].y + v[e].z + v[e].w;
        s2 += v[e].x * v[e].x + v[e].y * v[e].y + v[e].z * v[e].z + v[e].w * v[e].w;
    }
    #pragma unroll
    for (int o = 16; o > 0; o >>= 1) {
        s  += __shfl_xor_sync(0xffffffffu, s, o);
        s2 += __shfl_xor_sync(0xffffffffu, s2, o);
    }
    float mean = s * (1.f / W);
    float var = s2 * (1.f / W) - mean * mean;
    float inv = rsqrtf(var + LN_EPS);

    #pragma unroll
    for (int e = 0; e < E; e++) {
        int c4 = (lane + e * 32) * 4;
        float4 gg = *(const float4*)(g + c4);
        float4 bb = *(const float4*)(b + c4);
        float4 o;
        o.x = (v[e].x - mean) * inv * gg.x + bb.x;
        o.y = (v[e].y - mean) * inv * gg.y + bb.y;
        o.z = (v[e].z - mean) * inv * gg.z + bb.z;
        o.w = (v[e].w - mean) * inv * gg.w + bb.w;
        if (DOELU) {
            o.x = o.x > 0.f ? o.x : expm1f(o.x);
            o.y = o.y > 0.f ? o.y : expm1f(o.y);
            o.z = o.z > 0.f ? o.z : expm1f(o.z);
            o.w = o.w > 0.f ? o.w : expm1f(o.w);
        }
        uint2 u;
        *(bf162*)&u.x = __floats2bfloat162_rn(o.x, o.y);
        *(bf162*)&u.y = __floats2bfloat162_rn(o.z, o.w);
        ((uint2*)(outb + row * W))[lane + e * 32] = u;
    }
}

// ---------------------------------------------------------------------------
// Small kernels
// ---------------------------------------------------------------------------
__device__ __forceinline__ int read_t(const void* p) {
    int v = *(const int*)p;
    if (v >= 3 && v < 1000000) return v;
    float f = *(const float*)p;
    return (int)(f + 0.5f);
}

__device__ __forceinline__ float blk_sum(float v, float* red) {
    int tid = threadIdx.x;
    red[tid] = v; __syncthreads();
    #pragma unroll
    for (int s = 128; s > 0; s >>= 1) {
        if (tid < s) red[tid] += red[tid + s];
        __syncthreads();
    }
    float r = red[0]; __syncthreads();
    return r;
}
__device__ __forceinline__ float blk_max(float v, float* red) {
    int tid = threadIdx.x;
    red[tid] = v; __syncthreads();
    #pragma unroll
    for (int s = 128; s > 0; s >>= 1) {
        if (tid < s) red[tid] = fmaxf(red[tid], red[tid + s]);
        __syncthreads();
    }
    float r = red[0]; __syncthreads();
    return r;
}

__global__ void prep_kernel(const void* __restrict__ tptr,
                            const float* __restrict__ query,
                            const float* __restrict__ qkv_w,
                            const float* __restrict__ qkv_b) {
    int t = read_t(tptr);
    if (blockIdx.x == 0) {
        int j = threadIdx.x;
        const float* qrow = query + (size_t)(t - 3) * H_;
        float acc = qkv_b[j];
        #pragma unroll 4
        for (int i = 0; i < H_; i++)
            acc += qrow[i] * qkv_w[(size_t)i * 3 * H_ + j];
        d_qv[j] = acc;
    } else {
        #pragma unroll
        for (int r = 0; r < 2; r++) {
            int i = threadIdx.x + r * 256;
            int half = (i < H_) ? i : (i - H_);
            float fr  = expf(-logf(10000.f) * (float)half / (float)H_);
            float ang = (float)t * fr;
            d_te[i] = (i < H_) ? sinf(ang) : cosf(ang);
        }
    }
}

// Attention over bf16 kv
__global__ __launch_bounds__(256)
void attn_kernel(const bf16* __restrict__ kv) {
    int b = blockIdx.x, h = blockIdx.y;
    __shared__ float lg[N_];
    __shared__ float qs[HD];
    __shared__ float red[256];
    __shared__ float vred[8][HD];

    int tid = threadIdx.x;
    if (tid < HD) qs[tid] = d_qv[h * HD + tid];
    __syncthreads();

    const float scale = rsqrtf((float)HD);
    float lmax = -INFINITY;
    for (int n = tid; n < N_; n += 256) {
        const bf162* kp = (const bf162*)(kv + (size_t)(b * N_ + n) * 2 * H_ + h * HD);
        float dot = 0.f;
        #pragma unroll
        for (int d2 = 0; d2 < HD / 2; d2++) {
            float2 f = __bfloat1622float2(kp[d2]);
            dot += qs[d2 * 2] * f.x + qs[d2 * 2 + 1] * f.y;
        }
        dot *= scale;
        lg[n] = dot;
        lmax = fmaxf(lmax, dot);
    }
    float m = blk_max(lmax, red);

    float lsum = 0.f;
    for (int n = tid; n < N_; n += 256) {
        float p = expf(lg[n] - m);
        lg[n] = p;
        lsum += p;
    }
    float ssum = blk_sum(lsum, red);

    int w = tid >> 5, lane = tid & 31;
    float acc = 0.f;
    for (int n = w; n < N_; n += 8)
        acc += lg[n] * __bfloat162float(
            kv[(size_t)(b * N_ + n) * 2 * H_ + H_ + h * HD + lane]);
    vred[w][lane] = acc;
    __syncthreads();
    if (w == 0) {
        float s = 0.f;
        #pragma unroll
        for (int i = 0; i < 8; i++) s += vred[i][lane];
        d_ctx[b * H_ + h * HD + lane] = s / ssum;
    }
}

__global__ __launch_bounds__(256)
void outproj_kernel(const float* __restrict__ out_w,
                    const float* __restrict__ out_b) {
    int b = blockIdx.x, j = threadIdx.x;
    __shared__ float cs[H_];
    cs[j] = d_ctx[b * H_ + j];
    __syncthreads();
    float acc = out_b[j];
    #pragma unroll 4
    for (int i = 0; i < H_; i++) acc += cs[i] * out_w[(size_t)i * H_ + j];
    d_nf[b * H_ + j] = acc;
}

// e[b,n,:] = concat(new_feat[b], max(x[b,n], x[b,parent])) + te  -> bf16
// x is bf16 (d_xb)
__global__ __launch_bounds__(128)
void edge_kernel(const bf16* __restrict__ x, const int* __restrict__ eidx) {
    int row = blockIdx.x;
    int b = row / (N_ - 1), n = row % (N_ - 1);
    int pid = eidx[((size_t)b * N_ + n) * 2];
    int tid = threadIdx.x;

    bf16* ep = d_eb + (size_t)row * 2 * H_ + tid * 4;
    const float4* tep = (const float4*)d_te;
    float4 o;

    if (tid < 64) {
        const float4* nfp = (const float4*)(d_nf + b * H_);
        float4 v = nfp[tid], t4 = tep[tid];
        o = make_float4(v.x + t4.x, v.y + t4.y, v.z + t4.z, v.w + t4.w);
    } else {
        int c = tid - 64;
        uint2 cu = ((const uint2*)(x + (size_t)(b * N_ + n) * H_))[c];
        uint2 pu = ((const uint2*)(x + (size_t)(b * N_ + pid) * H_))[c];
        float2 c0 = __bfloat1622float2(*(bf162*)&cu.x);
        float2 c1 = __bfloat1622float2(*(bf162*)&cu.y);
        float2 p0 = __bfloat1622float2(*(bf162*)&pu.x);
        float2 p1 = __bfloat1622float2(*(bf162*)&pu.y);
        float4 t4 = tep[tid];
        o = make_float4(fmaxf(c0.x, p0.x) + t4.x, fmaxf(c0.y, p0.y) + t4.y,
                        fmaxf(c1.x, p1.x) + t4.z, fmaxf(c1.y, p1.y) + t4.w);
    }
    *(bf162*)(ep)     = __floats2bfloat162_rn(o.x, o.y);
    *(bf162*)(ep + 2) = __floats2bfloat162_rn(o.z, o.w);
}

// logits = h @ r3_w + r3_b   (h in bf16)
__global__ __launch_bounds__(256)
void matvec_kernel(const bf16* __restrict__ h, const float* __restrict__ w,
                   const float* __restrict__ b) {
    __shared__ float ws[512];
    int tid = threadIdx.x;
    ws[tid] = w[tid];
    ws[tid + 256] = w[tid + 256];
    __syncthreads();

    int wid = tid >> 5, lane = tid & 31;
    int row = blockIdx.x * 8 + wid;
    const bf162* p = (const bf162*)(h + (size_t)row * 512);
    float s = 0.f;
    #pragma unroll
    for (int i = 0; i < 8; i++) {
        int kp = lane + i * 32;
        float2 f = __bfloat1622float2(p[kp]);
        s += f.x * ws[kp * 2] + f.y * ws[kp * 2 + 1];
    }
    #pragma unroll
    for (int o = 16; o > 0; o >>= 1) s += __shfl_down_sync(0xffffffffu, s, o);
    if (lane == 0) d_lg[row] = s + b[0];
}

__global__ __launch_bounds__(256)
void lsm_kernel(float* __restrict__ out) {
    int b = blockIdx.x, tid = threadIdx.x;
    const int L = N_ - 1;
    const float* p = d_lg + (size_t)b * L;
    __shared__ float red[256];

    float m = -INFINITY;
    for (int n = tid; n < L; n += 256) m = fmaxf(m, p[n]);
    float mm = blk_max(m, red);

    float s = 0.f;
    for (int n = tid; n < L; n += 256) s += expf(p[n] - mm);
    float ls = mm + logf(blk_sum(s, red));

    for (int n = tid; n < L; n += 256)
        out[(size_t)b * L + n] = p[n] - ls;
}

// ---------------------------------------------------------------------------
// kernel_launch
// ---------------------------------------------------------------------------
extern "C" void kernel_launch(void* const* d_in, const int* in_sizes, int n_in,
                              void* d_out, int out_size) {
    const float* nf_in  = (const float*)d_in[0];
    const int*   eidx   = (const int*)  d_in[1];
    const void*  tptr   =               d_in[2];
    const float* query  = (const float*)d_in[3];
    const float* mlp_w1 = (const float*)d_in[4];
    const float* mlp_b1 = (const float*)d_in[5];
    const float* mlp_w2 = (const float*)d_in[6];
    const float* mlp_b2 = (const float*)d_in[7];
    const float* mlp_g  = (const float*)d_in[8];
    const float* mlp_b  = (const float*)d_in[9];
    const float* qkv_w  = (const float*)d_in[10];
    const float* qkv_b  = (const float*)d_in[11];
    const float* out_w  = (const float*)d_in[12];
    const float* out_b  = (const float*)d_in[13];
    const float* r1_w   = (const float*)d_in[14];
    const float* r1_b   = (const float*)d_in[15];
    const float* r1_g   = (const float*)d_in[16];
    const float* r1_bb  = (const float*)d_in[17];
    const float* r2_w   = (const float*)d_in[18];
    const float* r2_b   = (const float*)d_in[19];
    const float* r2_g   = (const float*)d_in[20];
    const float* r2_bb  = (const float*)d_in[21];
    const float* r3_w   = (const float*)d_in[22];
    const float* r3_b   = (const float*)d_in[23];
    float* out = (float*)d_out;

    bf16 *p_nfb, *p_t1b, *p_x2b, *p_xb, *p_kvb, *p_eb, *p_r1b, *p_hb;
    bf16 *p_w1t, *p_w2t, *p_kvwt, *p_r1wt, *p_r2wt;
    cudaGetSymbolAddress((void**)&p_nfb, d_nfb);
    cudaGetSymbolAddress((void**)&p_t1b, d_t1b);
    cudaGetSymbolAddress((void**)&p_x2b, d_x2b);
    cudaGetSymbolAddress((void**)&p_xb,  d_xb);
    cudaGetSymbolAddress((void**)&p_kvb, d_kvb);
    cudaGetSymbolAddress((void**)&p_eb,  d_eb);
    cudaGetSymbolAddress((void**)&p_r1b, d_r1b);
    cudaGetSymbolAddress((void**)&p_hb,  d_hb);
    cudaGetSymbolAddress((void**)&p_w1t,  d_w1t);
    cudaGetSymbolAddress((void**)&p_w2t,  d_w2t);
    cudaGetSymbolAddress((void**)&p_kvwt, d_kvwt);
    cudaGetSymbolAddress((void**)&p_r1wt, d_r1wt);
    cudaGetSymbolAddress((void**)&p_r2wt, d_r2wt);

    cudaFuncSetAttribute(tc_gemm_kernel<0>,
                         cudaFuncAttributeMaxDynamicSharedMemorySize, GEMM_SMEM);
    cudaFuncSetAttribute(tc_gemm_kernel<1>,
                         cudaFuncAttributeMaxDynamicSharedMemorySize, GEMM_SMEM);

    // Weight transposes -> bf16 [N][K]
    transpose_kernel<<<dim3(NTIPS / 32, H_ / 32), 256>>>(mlp_w1, p_w1t, NTIPS, H_, H_);
    transpose_kernel<<<dim3(H_ / 32, H_ / 32), 256>>>(mlp_w2, p_w2t, H_, H_, H_);
    transpose_kernel<<<dim3(H_ / 32, 2 * H_ / 32), 256>>>(qkv_w + H_, p_kvwt, H_, 2 * H_, 3 * H_);
    transpose_kernel<<<dim3(2 * H_ / 32, 2 * H_ / 32), 256>>>(r1_w, p_r1wt, 2 * H_, 2 * H_, 2 * H_);
    transpose_kernel<<<dim3(2 * H_ / 32, 2 * H_ / 32), 256>>>(r2_w, p_r2wt, 2 * H_, 2 * H_, 2 * H_);

    // node_features -> bf16
    cvt_kernel<<<(size_t)M1 * NTIPS / 1024, 256>>>(nf_in, p_nfb);

    // Stage 1: MLP
    tc_gemm_kernel<1><<<dim3(H_ / 128, M1 / 128), 256, GEMM_SMEM>>>(
        p_nfb, p_w1t, mlp_b1, p_t1b, M1, H_, NTIPS);
    tc_gemm_kernel<0><<<dim3(H_ / 128, M1 / 128), 256, GEMM_SMEM>>>(
        p_t1b, p_w2t, mlp_b2, p_x2b, M1, H_, H_);
    ln_bf16_kernel<H_, false><<<M1 / 8, 256>>>(p_x2b, p_xb, mlp_g, mlp_b);

    // q vector + time embedding
    prep_kernel<<<2, 256>>>(tptr, query, qkv_w, qkv_b);

    // kv projection -> bf16
    tc_gemm_kernel<0><<<dim3(2 * H_ / 128, M1 / 128), 256, GEMM_SMEM>>>(
        p_xb, p_kvwt, qkv_b + H_, p_kvb, M1, 2 * H_, H_);

    // Attention + output projection
    attn_kernel<<<dim3(B_, NH), 256>>>(p_kvb);
    outproj_kernel<<<B_, 256>>>(out_w, out_b);

    // Edge features + time embedding -> bf16
    edge_kernel<<<M2, 128>>>(p_xb, eidx);

    // Readout stack
    tc_gemm_kernel<0><<<dim3(2 * H_ / 128, M2 / 128), 256, GEMM_SMEM>>>(
        p_eb, p_r1wt, r1_b, p_r1b, M2, 2 * H_, 2 * H_);
    ln_bf16_kernel<2 * H_, true><<<M2 / 8, 256>>>(p_r1b, p_hb, r1_g, r1_bb);

    tc_gemm_kernel<0><<<dim3(2 * H_ / 128, M2 / 128), 256, GEMM_SMEM>>>(
        p_hb, p_r2wt, r2_b, p_r1b, M2, 2 * H_, 2 * H_);
    ln_bf16_kernel<2 * H_, true><<<M2 / 8, 256>>>(p_r1b, p_eb, r2_g, r2_bb);

    matvec_kernel<<<M2 / 8, 256>>>(p_eb, r3_w, r3_b);
    lsm_kernel<<<B_, 256>>>(out);
}

// round 17
// speedup vs baseline: 1.0900x; 1.0712x over previous
#include <cuda_runtime.h>
#include <cuda_bf16.h>
#include <math.h>
#include <stdint.h>

// ---------------------------------------------------------------------------
// Problem constants (fixed shapes)
// ---------------------------------------------------------------------------
#define B_    128
#define N_    1022
#define NTIPS 512
#define H_    256
#define NH    8
#define HD    32
#define M1    (B_ * N_)        // 130816
#define M2    (B_ * (N_ - 1)) // 130688
#define LN_EPS 1e-5f

typedef __nv_bfloat16  bf16;
typedef __nv_bfloat162 bf162;

// ---------------------------------------------------------------------------
// Scratch (static device globals)
// ---------------------------------------------------------------------------
__device__ bf16  d_nfb[(size_t)M1 * NTIPS];     // node_features bf16
__device__ bf16  d_t1b[(size_t)M1 * H_];        // elu(nf@w1+b1)
__device__ bf16  d_x2b[(size_t)M1 * H_];        // gemm2 out (pre-LN)
__device__ bf16  d_xb [(size_t)M1 * H_];        // ln1 out (kv A, edge reads)
__device__ bf16  d_kvb[(size_t)M1 * 2 * H_];    // kv (attn reads)
__device__ bf16  d_eb [(size_t)M2 * H_];        // edge max part ONLY (r1 A)
__device__ bf16  d_r1b[(size_t)M2 * 2 * H_];    // r1 out pre-LN; reused r2 out
__device__ bf16  d_hb [(size_t)M2 * 2 * H_];    // ln2 out (r2 A); reused ln3 out
__device__ float d_qv [H_];
__device__ float d_te [2 * H_];
__device__ float d_ctx[B_ * H_];
__device__ float d_nf [B_ * H_];
__device__ float d_bias1[B_ * 2 * H_];          // folded r1 bias rows
__device__ float d_lg [M2];
// transposed bf16 weights ([N][K], K contiguous)
__device__ bf16 d_w1t [H_ * NTIPS];
__device__ bf16 d_w2t [H_ * H_];
__device__ bf16 d_kvwt[2 * H_ * H_];
__device__ bf16 d_r1wt[2 * H_ * H_];            // W[256:512,:]^T -> [512][256]
__device__ bf16 d_r2wt[2 * H_ * 2 * H_];

// ---------------------------------------------------------------------------
// helpers
// ---------------------------------------------------------------------------
__device__ __forceinline__ uint32_t smem_u32(const void* p) {
    uint32_t a;
    asm("{ .reg .u64 t; cvta.to.shared.u64 t, %1; cvt.u32.u64 %0, t; }"
        : "=r"(a) : "l"(p));
    return a;
}

__device__ __forceinline__ void mma_bf16(float* c, const uint32_t* a,
                                         const uint32_t* b) {
    asm volatile(
        "mma.sync.aligned.m16n8k16.row.col.f32.bf16.bf16.f32 "
        "{%0,%1,%2,%3}, {%4,%5,%6,%7}, {%8,%9}, {%0,%1,%2,%3};"
        : "+f"(c[0]), "+f"(c[1]), "+f"(c[2]), "+f"(c[3])
        : "r"(a[0]), "r"(a[1]), "r"(a[2]), "r"(a[3]), "r"(b[0]), "r"(b[1]));
}

#define CP_ASYNC16(dst, src) \
    asm volatile("cp.async.cg.shared.global [%0], [%1], 16;" \
        :: "r"(dst), "l"(src) : "memory")
#define CP_COMMIT() asm volatile("cp.async.commit_group;" ::: "memory")
#define CP_WAIT1()  asm volatile("cp.async.wait_group 1;" ::: "memory")
#define CP_WAIT0()  asm volatile("cp.async.wait_group 0;" ::: "memory")

// ---------------------------------------------------------------------------
// bf16 tensor-core GEMM (R11-proven config): C = act(A @ Bt^T + bias), bf16 out
// Block tile 128x128, BK=32, 256 threads (8 warps, 2m x 4n), warp 64x32,
// mma.m16n8k16.bf16, scalar LDS frags, 2-stage cp.async, 2 CTAs/SM.
// BROW: bias is per-batch rows [B_][Nn], batch = row / (N_-1).
// ---------------------------------------------------------------------------
#define BKC 32
#define LDS_STR 20
#define TILE_U32 (128 * LDS_STR)                 // 2560
#define GEMM_SMEM (2 * 2 * TILE_U32 * 4)         // 40960 bytes

template <int ACT, bool BROW>  // ACT: 0 none, 1 elu
__global__ __launch_bounds__(256, 2)
void tc_gemm_kernel(const bf16* __restrict__ A, const bf16* __restrict__ Bt,
                    const float* __restrict__ bias, bf16* __restrict__ C,
                    int M, int Nn, int K) {
    extern __shared__ uint32_t smem[];

    const int tid = threadIdx.x;
    const int bn = blockIdx.x, bm = blockIdx.y;

    // copy mapping: row = tid>>1 (0..127), 2x16B segs at (tid&1)*32 bytes
    const int crow = tid >> 1;
    const int chalf = tid & 1;
    const bf16* Ag = A + (size_t)(bm * 128 + crow) * K + chalf * 16;
    const bf16* Bg = Bt + (size_t)(bn * 128 + crow) * K + chalf * 16;

    const uint32_t sbase = smem_u32(smem);
    const uint32_t cbyte = (uint32_t)(crow * LDS_STR) * 4 + chalf * 32;

    // warp mapping
    const int wid = tid >> 5, lane = tid & 31;
    const int wm = (wid & 1) * 64;
    const int wn = (wid >> 1) * 32;
    const int g = lane >> 2, tig = lane & 3;

    float c[4][4][4];
    #pragma unroll
    for (int mt = 0; mt < 4; mt++)
        #pragma unroll
        for (int nt = 0; nt < 4; nt++)
            #pragma unroll
            for (int i = 0; i < 4; i++) c[mt][nt][i] = 0.f;

    const int NC = K >> 5;

    // prologue: copy stage 0
    {
        const uint32_t ad = sbase + cbyte;
        const uint32_t bd = ad + TILE_U32 * 4;
        CP_ASYNC16(ad,      Ag);
        CP_ASYNC16(ad + 16, Ag + 8);
        CP_ASYNC16(bd,      Bg);
        CP_ASYNC16(bd + 16, Bg + 8);
        CP_COMMIT();
    }

    for (int kc = 0; kc < NC; kc++) {
        const int cur = kc & 1;

        __syncthreads();  // all warps done reading buffer cur^1 before overwrite
        if (kc + 1 < NC) {
            const uint32_t ad = sbase + (uint32_t)(cur ^ 1) * 2 * TILE_U32 * 4 + cbyte;
            const uint32_t bd = ad + TILE_U32 * 4;
            const bf16* as = Ag + (kc + 1) * BKC;
            const bf16* bs = Bg + (kc + 1) * BKC;
            CP_ASYNC16(ad,      as);
            CP_ASYNC16(ad + 16, as + 8);
            CP_ASYNC16(bd,      bs);
            CP_ASYNC16(bd + 16, bs + 8);
            CP_COMMIT();
            CP_WAIT1();
        } else {
            CP_WAIT0();
        }
        __syncthreads();

        const uint32_t* Ab = smem + cur * 2 * TILE_U32;
        const uint32_t* Bb = Ab + TILE_U32;
        #pragma unroll
        for (int ks = 0; ks < 2; ks++) {      // two k16 steps per BK=32
            const int p0 = ks * 8;
            uint32_t a[4][4], b[4][2];
            #pragma unroll
            for (int mt = 0; mt < 4; mt++) {
                int r0 = wm + mt * 16 + g;
                a[mt][0] = Ab[(r0    ) * LDS_STR + p0 + tig];
                a[mt][1] = Ab[(r0 + 8) * LDS_STR + p0 + tig];
                a[mt][2] = Ab[(r0    ) * LDS_STR + p0 + tig + 4];
                a[mt][3] = Ab[(r0 + 8) * LDS_STR + p0 + tig + 4];
            }
            #pragma unroll
            for (int nt = 0; nt < 4; nt++) {
                int n0 = wn + nt * 8 + g;
                b[nt][0] = Bb[n0 * LDS_STR + p0 + tig];
                b[nt][1] = Bb[n0 * LDS_STR + p0 + tig + 4];
            }
            #pragma unroll
            for (int mt = 0; mt < 4; mt++)
                #pragma unroll
                for (int nt = 0; nt < 4; nt++)
                    mma_bf16(c[mt][nt], a[mt], b[nt]);
        }
    }

    // Epilogue: bias (flat or per-batch row) + optional ELU; bf16 stores
    #pragma unroll
    for (int mt = 0; mt < 4; mt++) {
        #pragma unroll
        for (int nt = 0; nt < 4; nt++) {
            int col = bn * 128 + wn + nt * 8 + 2 * tig;
            #pragma unroll
            for (int half = 0; half < 2; half++) {
                int row = bm * 128 + wm + mt * 16 + g + half * 8;
                const float* bp = BROW
                    ? bias + (size_t)(row / (N_ - 1)) * Nn : bias;
                float v0 = c[mt][nt][half * 2 + 0] + __ldg(bp + col);
                float v1 = c[mt][nt][half * 2 + 1] + __ldg(bp + col + 1);
                if (ACT == 1) {
                    v0 = v0 > 0.f ? v0 : expm1f(v0);
                    v1 = v1 > 0.f ? v1 : expm1f(v1);
                }
                *(bf162*)(C + (size_t)row * Nn + col) =
                    __floats2bfloat162_rn(v0, v1);
            }
        }
    }
}

// ---------------------------------------------------------------------------
// Weight transpose to bf16: out[n*K+k] = bf16(in[k*ldin + n])
// ---------------------------------------------------------------------------
__global__ __launch_bounds__(256)
void transpose_kernel(const float* __restrict__ in, bf16* __restrict__ out,
                      int K, int N, int ldin) {
    __shared__ float tile[32][33];
    int k0 = blockIdx.x * 32, n0 = blockIdx.y * 32;
    int x = threadIdx.x & 31, y = (threadIdx.x >> 5) * 4;
    #pragma unroll
    for (int i = 0; i < 4; i++)
        tile[y + i][x] = in[(size_t)(k0 + y + i) * ldin + n0 + x];
    __syncthreads();
    #pragma unroll
    for (int i = 0; i < 4; i++)
        out[(size_t)(n0 + y + i) * K + k0 + x] =
            __float2bfloat16_rn(tile[x][y + i]);
}

// ---------------------------------------------------------------------------
// fp32 -> bf16 elementwise convert (for node_features)
// ---------------------------------------------------------------------------
__global__ __launch_bounds__(256)
void cvt_kernel(const float* __restrict__ in, bf16* __restrict__ out) {
    size_t i = ((size_t)blockIdx.x * 256 + threadIdx.x) * 4;
    float4 v = *(const float4*)(in + i);
    *(bf162*)(out + i)     = __floats2bfloat162_rn(v.x, v.y);
    *(bf162*)(out + i + 2) = __floats2bfloat162_rn(v.z, v.w);
}

// ---------------------------------------------------------------------------
// Warp-per-row LayerNorm: bf16 in -> bf16 out, optional fused ELU.
// ---------------------------------------------------------------------------
template <int W, bool DOELU>
__global__ __launch_bounds__(256)
void ln_bf16_kernel(const bf16* __restrict__ in, bf16* __restrict__ outb,
                    const float* __restrict__ g, const float* __restrict__ b) {
    constexpr int E = W / 128;
    int wid = threadIdx.x >> 5, lane = threadIdx.x & 31;
    size_t row = (size_t)blockIdx.x * 8 + wid;
    const uint2* pin = (const uint2*)(in + row * W);

    float4 v[E];
    float s = 0.f, s2 = 0.f;
    #pragma unroll
    for (int e = 0; e < E; e++) {
        uint2 u = pin[lane + e * 32];
        float2 lo = __bfloat1622float2(*(bf162*)&u.x);
        float2 hi = __bfloat1622float2(*(bf162*)&u.y);
        v[e] = make_float4(lo.x, lo.y, hi.x, hi.y);
        s  += v[e].x + v[e].y + v[e].z + v[e].w;
        s2 += v[e].x * v[e].x + v[e].y * v[e].y + v[e].z * v[e].z + v[e].w * v[e].w;
    }
    #pragma unroll
    for (int o = 16; o > 0; o >>= 1) {
        s  += __shfl_xor_sync(0xffffffffu, s, o);
        s2 += __shfl_xor_sync(0xffffffffu, s2, o);
    }
    float mean = s * (1.f / W);
    float var = s2 * (1.f / W) - mean * mean;
    float inv = rsqrtf(var + LN_EPS);

    #pragma unroll
    for (int e = 0; e < E; e++) {
        int c4 = (lane + e * 32) * 4;
        float4 gg = *(const float4*)(g + c4);
        float4 bb = *(const float4*)(b + c4);
        float4 o;
        o.x = (v[e].x - mean) * inv * gg.x + bb.x;
        o.y = (v[e].y - mean) * inv * gg.y + bb.y;
        o.z = (v[e].z - mean) * inv * gg.z + bb.z;
        o.w = (v[e].w - mean) * inv * gg.w + bb.w;
        if (DOELU) {
            o.x = o.x > 0.f ? o.x : expm1f(o.x);
            o.y = o.y > 0.f ? o.y : expm1f(o.y);
            o.z = o.z > 0.f ? o.z : expm1f(o.z);
            o.w = o.w > 0.f ? o.w : expm1f(o.w);
        }
        uint2 u;
        *(bf162*)&u.x = __floats2bfloat162_rn(o.x, o.y);
        *(bf162*)&u.y = __floats2bfloat162_rn(o.z, o.w);
        ((uint2*)(outb + row * W))[lane + e * 32] = u;
    }
}

// ---------------------------------------------------------------------------
// Small kernels
// ---------------------------------------------------------------------------
__device__ __forceinline__ int read_t(const void* p) {
    int v = *(const int*)p;
    if (v >= 3 && v < 1000000) return v;
    float f = *(const float*)p;
    return (int)(f + 0.5f);
}

__device__ __forceinline__ float blk_sum(float v, float* red) {
    int tid = threadIdx.x;
    red[tid] = v; __syncthreads();
    #pragma unroll
    for (int s = 128; s > 0; s >>= 1) {
        if (tid < s) red[tid] += red[tid + s];
        __syncthreads();
    }
    float r = red[0]; __syncthreads();
    return r;
}
__device__ __forceinline__ float blk_max(float v, float* red) {
    int tid = threadIdx.x;
    red[tid] = v; __syncthreads();
    #pragma unroll
    for (int s = 128; s > 0; s >>= 1) {
        if (tid < s) red[tid] = fmaxf(red[tid], red[tid + s]);
        __syncthreads();
    }
    float r = red[0]; __syncthreads();
    return r;
}

__global__ void prep_kernel(const void* __restrict__ tptr,
                            const float* __restrict__ query,
                            const float* __restrict__ qkv_w,
                            const float* __restrict__ qkv_b) {
    int t = read_t(tptr);
    if (blockIdx.x == 0) {
        int j = threadIdx.x;
        const float* qrow = query + (size_t)(t - 3) * H_;
        float acc = qkv_b[j];
        #pragma unroll 4
        for (int i = 0; i < H_; i++)
            acc += qrow[i] * qkv_w[(size_t)i * 3 * H_ + j];
        d_qv[j] = acc;
    } else {
        #pragma unroll
        for (int r = 0; r < 2; r++) {
            int i = threadIdx.x + r * 256;
            int half = (i < H_) ? i : (i - H_);
            float fr  = expf(-logf(10000.f) * (float)half / (float)H_);
            float ang = (float)t * fr;
            d_te[i] = (i < H_) ? sinf(ang) : cosf(ang);
        }
    }
}

// Attention over bf16 kv
__global__ __launch_bounds__(256)
void attn_kernel(const bf16* __restrict__ kv) {
    int b = blockIdx.x, h = blockIdx.y;
    __shared__ float lg[N_];
    __shared__ float qs[HD];
    __shared__ float red[256];
    __shared__ float vred[8][HD];

    int tid = threadIdx.x;
    if (tid < HD) qs[tid] = d_qv[h * HD + tid];
    __syncthreads();

    const float scale = rsqrtf((float)HD);
    float lmax = -INFINITY;
    for (int n = tid; n < N_; n += 256) {
        const bf162* kp = (const bf162*)(kv + (size_t)(b * N_ + n) * 2 * H_ + h * HD);
        float dot = 0.f;
        #pragma unroll
        for (int d2 = 0; d2 < HD / 2; d2++) {
            float2 f = __bfloat1622float2(kp[d2]);
            dot += qs[d2 * 2] * f.x + qs[d2 * 2 + 1] * f.y;
        }
        dot *= scale;
        lg[n] = dot;
        lmax = fmaxf(lmax, dot);
    }
    float m = blk_max(lmax, red);

    float lsum = 0.f;
    for (int n = tid; n < N_; n += 256) {
        float p = expf(lg[n] - m);
        lg[n] = p;
        lsum += p;
    }
    float ssum = blk_sum(lsum, red);

    int w = tid >> 5, lane = tid & 31;
    float acc = 0.f;
    for (int n = w; n < N_; n += 8)
        acc += lg[n] * __bfloat162float(
            kv[(size_t)(b * N_ + n) * 2 * H_ + H_ + h * HD + lane]);
    vred[w][lane] = acc;
    __syncthreads();
    if (w == 0) {
        float s = 0.f;
        #pragma unroll
        for (int i = 0; i < 8; i++) s += vred[i][lane];
        d_ctx[b * H_ + h * HD + lane] = s / ssum;
    }
}

__global__ __launch_bounds__(256)
void outproj_kernel(const float* __restrict__ out_w,
                    const float* __restrict__ out_b) {
    int b = blockIdx.x, j = threadIdx.x;
    __shared__ float cs[H_];
    cs[j] = d_ctx[b * H_ + j];
    __syncthreads();
    float acc = out_b[j];
    #pragma unroll 4
    for (int i = 0; i < H_; i++) acc += cs[i] * out_w[(size_t)i * H_ + j];
    d_nf[b * H_ + j] = acc;
}

// bias1[b][j] = r1_b[j] + sum_i val_i * r1_w[i][j]
// val_i = nf[b][i] + te[i]  (i<256),  te[i]  (i>=256)
__global__ __launch_bounds__(512)
void bias1_kernel(const float* __restrict__ r1_w,
                  const float* __restrict__ r1_b) {
    __shared__ float vals[512];
    int b = blockIdx.x, j = threadIdx.x;
    float v = d_te[j];
    if (j < H_) v += d_nf[b * H_ + j];
    vals[j] = v;
    __syncthreads();
    float acc = r1_b[j];
    #pragma unroll 4
    for (int i = 0; i < 2 * H_; i++)
        acc += vals[i] * r1_w[(size_t)i * 2 * H_ + j];
    d_bias1[b * 2 * H_ + j] = acc;
}

// edge max part only: d_eb[row][0:256] = max(x[b,n], x[b,parent])
// 4 rows per block (64 threads/row, uint2 = 4 bf16 each)
__global__ __launch_bounds__(256)
void edge_kernel(const bf16* __restrict__ x, const int* __restrict__ eidx) {
    int row = blockIdx.x * 4 + (threadIdx.x >> 6);
    int c = threadIdx.x & 63;
    int b = row / (N_ - 1), n = row % (N_ - 1);
    int pid = eidx[((size_t)b * N_ + n) * 2];
    uint2 cu = ((const uint2*)(x + (size_t)(b * N_ + n) * H_))[c];
    uint2 pu = ((const uint2*)(x + (size_t)(b * N_ + pid) * H_))[c];
    uint2 o;
    *(bf162*)&o.x = __hmax2(*(bf162*)&cu.x, *(bf162*)&pu.x);
    *(bf162*)&o.y = __hmax2(*(bf162*)&cu.y, *(bf162*)&pu.y);
    ((uint2*)(d_eb + (size_t)row * H_))[c] = o;
}

// logits = h @ r3_w + r3_b   (h in bf16)
__global__ __launch_bounds__(256)
void matvec_kernel(const bf16* __restrict__ h, const float* __restrict__ w,
                   const float* __restrict__ b) {
    __shared__ float ws[512];
    int tid = threadIdx.x;
    ws[tid] = w[tid];
    ws[tid + 256] = w[tid + 256];
    __syncthreads();

    int wid = tid >> 5, lane = tid & 31;
    int row = blockIdx.x * 8 + wid;
    const bf162* p = (const bf162*)(h + (size_t)row * 512);
    float s = 0.f;
    #pragma unroll
    for (int i = 0; i < 8; i++) {
        int kp = lane + i * 32;
        float2 f = __bfloat1622float2(p[kp]);
        s += f.x * ws[kp * 2] + f.y * ws[kp * 2 + 1];
    }
    #pragma unroll
    for (int o = 16; o > 0; o >>= 1) s += __shfl_down_sync(0xffffffffu, s, o);
    if (lane == 0) d_lg[row] = s + b[0];
}

__global__ __launch_bounds__(256)
void lsm_kernel(float* __restrict__ out) {
    int b = blockIdx.x, tid = threadIdx.x;
    const int L = N_ - 1;
    const float* p = d_lg + (size_t)b * L;
    __shared__ float red[256];

    float m = -INFINITY;
    for (int n = tid; n < L; n += 256) m = fmaxf(m, p[n]);
    float mm = blk_max(m, red);

    float s = 0.f;
    for (int n = tid; n < L; n += 256) s += expf(p[n] - mm);
    float ls = mm + logf(blk_sum(s, red));

    for (int n = tid; n < L; n += 256)
        out[(size_t)b * L + n] = p[n] - ls;
}

// ---------------------------------------------------------------------------
// kernel_launch
// ---------------------------------------------------------------------------
extern "C" void kernel_launch(void* const* d_in, const int* in_sizes, int n_in,
                              void* d_out, int out_size) {
    const float* nf_in  = (const float*)d_in[0];
    const int*   eidx   = (const int*)  d_in[1];
    const void*  tptr   =               d_in[2];
    const float* query  = (const float*)d_in[3];
    const float* mlp_w1 = (const float*)d_in[4];
    const float* mlp_b1 = (const float*)d_in[5];
    const float* mlp_w2 = (const float*)d_in[6];
    const float* mlp_b2 = (const float*)d_in[7];
    const float* mlp_g  = (const float*)d_in[8];
    const float* mlp_b  = (const float*)d_in[9];
    const float* qkv_w  = (const float*)d_in[10];
    const float* qkv_b  = (const float*)d_in[11];
    const float* out_w  = (const float*)d_in[12];
    const float* out_b  = (const float*)d_in[13];
    const float* r1_w   = (const float*)d_in[14];
    const float* r1_b   = (const float*)d_in[15];
    const float* r1_g   = (const float*)d_in[16];
    const float* r1_bb  = (const float*)d_in[17];
    const float* r2_w   = (const float*)d_in[18];
    const float* r2_b   = (const float*)d_in[19];
    const float* r2_g   = (const float*)d_in[20];
    const float* r2_bb  = (const float*)d_in[21];
    const float* r3_w   = (const float*)d_in[22];
    const float* r3_b   = (const float*)d_in[23];
    float* out = (float*)d_out;

    bf16 *p_nfb, *p_t1b, *p_x2b, *p_xb, *p_kvb, *p_eb, *p_r1b, *p_hb;
    bf16 *p_w1t, *p_w2t, *p_kvwt, *p_r1wt, *p_r2wt;
    float *p_bias1;
    cudaGetSymbolAddress((void**)&p_nfb, d_nfb);
    cudaGetSymbolAddress((void**)&p_t1b, d_t1b);
    cudaGetSymbolAddress((void**)&p_x2b, d_x2b);
    cudaGetSymbolAddress((void**)&p_xb,  d_xb);
    cudaGetSymbolAddress((void**)&p_kvb, d_kvb);
    cudaGetSymbolAddress((void**)&p_eb,  d_eb);
    cudaGetSymbolAddress((void**)&p_r1b, d_r1b);
    cudaGetSymbolAddress((void**)&p_hb,  d_hb);
    cudaGetSymbolAddress((void**)&p_bias1, d_bias1);
    cudaGetSymbolAddress((void**)&p_w1t,  d_w1t);
    cudaGetSymbolAddress((void**)&p_w2t,  d_w2t);
    cudaGetSymbolAddress((void**)&p_kvwt, d_kvwt);
    cudaGetSymbolAddress((void**)&p_r1wt, d_r1wt);
    cudaGetSymbolAddress((void**)&p_r2wt, d_r2wt);

    cudaFuncSetAttribute(tc_gemm_kernel<0, false>,
                         cudaFuncAttributeMaxDynamicSharedMemorySize, GEMM_SMEM);
    cudaFuncSetAttribute(tc_gemm_kernel<1, false>,
                         cudaFuncAttributeMaxDynamicSharedMemorySize, GEMM_SMEM);
    cudaFuncSetAttribute(tc_gemm_kernel<0, true>,
                         cudaFuncAttributeMaxDynamicSharedMemorySize, GEMM_SMEM);

    // Weight transposes -> bf16 [N][K]
    transpose_kernel<<<dim3(NTIPS / 32, H_ / 32), 256>>>(mlp_w1, p_w1t, NTIPS, H_, H_);
    transpose_kernel<<<dim3(H_ / 32, H_ / 32), 256>>>(mlp_w2, p_w2t, H_, H_, H_);
    transpose_kernel<<<dim3(H_ / 32, 2 * H_ / 32), 256>>>(qkv_w + H_, p_kvwt, H_, 2 * H_, 3 * H_);
    // r1: only rows 256..511 of r1_w (edge input dims) -> [512 N][256 K]
    transpose_kernel<<<dim3(H_ / 32, 2 * H_ / 32), 256>>>(
        r1_w + (size_t)H_ * 2 * H_, p_r1wt, H_, 2 * H_, 2 * H_);
    transpose_kernel<<<dim3(2 * H_ / 32, 2 * H_ / 32), 256>>>(r2_w, p_r2wt, 2 * H_, 2 * H_, 2 * H_);

    // node_features -> bf16
    cvt_kernel<<<(size_t)M1 * NTIPS / 1024, 256>>>(nf_in, p_nfb);

    // Stage 1: MLP
    tc_gemm_kernel<1, false><<<dim3(H_ / 128, M1 / 128), 256, GEMM_SMEM>>>(
        p_nfb, p_w1t, mlp_b1, p_t1b, M1, H_, NTIPS);
    tc_gemm_kernel<0, false><<<dim3(H_ / 128, M1 / 128), 256, GEMM_SMEM>>>(
        p_t1b, p_w2t, mlp_b2, p_x2b, M1, H_, H_);
    ln_bf16_kernel<H_, false><<<M1 / 8, 256>>>(p_x2b, p_xb, mlp_g, mlp_b);

    // q vector + time embedding
    prep_kernel<<<2, 256>>>(tptr, query, qkv_w, qkv_b);

    // kv projection -> bf16
    tc_gemm_kernel<0, false><<<dim3(2 * H_ / 128, M1 / 128), 256, GEMM_SMEM>>>(
        p_xb, p_kvwt, qkv_b + H_, p_kvb, M1, 2 * H_, H_);

    // Attention + output projection
    attn_kernel<<<dim3(B_, NH), 256>>>(p_kvb);
    outproj_kernel<<<B_, 256>>>(out_w, out_b);

    // Folded per-batch bias rows for r1
    bias1_kernel<<<B_, 512>>>(r1_w, r1_b);

    // Edge max part (independent of attention)
    edge_kernel<<<M2 / 4, 256>>>(p_xb, eidx);

    // Readout stack: r1 = edge @ W[256:,:] + bias1[b]  (K=256 now!)
    tc_gemm_kernel<0, true><<<dim3(2 * H_ / 128, M2 / 128), 256, GEMM_SMEM>>>(
        p_eb, p_r1wt, p_bias1, p_r1b, M2, 2 * H_, H_);
    ln_bf16_kernel<2 * H_, true><<<M2 / 8, 256>>>(p_r1b, p_hb, r1_g, r1_bb);

    tc_gemm_kernel<0, false><<<dim3(2 * H_ / 128, M2 / 128), 256, GEMM_SMEM>>>(
        p_hb, p_r2wt, r2_b, p_r1b, M2, 2 * H_, 2 * H_);
    ln_bf16_kernel<2 * H_, true><<<M2 / 8, 256>>>(p_r1b, p_hb, r2_g, r2_bb);

    matvec_kernel<<<M2 / 8, 256>>>(p_hb, r3_w, r3_b);
    lsm_kernel<<<B_, 256>>>(out);
}